// round 11
// baseline (speedup 1.0000x reference)
#include <cuda_runtime.h>
#include <cuda_fp16.h>
#include <mma.h>
#include <math.h>

using namespace nvcuda;

#define NN 16384
#define EE 131072
#define GG 32
#define BN_EPS 1e-5f

// ---------------- scratch (device globals: no allocation allowed) ----------
__device__ float g_bufA[NN * 512];    // GAT per-head agg [N,512] (32 MB)
__device__ float g_bufB[NN * 512];    // packed sage / agg        (32 MB)
__device__ float g_bufC[NN * 512];    // pre-BN buffers           (32 MB)
__device__ float g_bufD[NN * 512];    // post-BN layer2 output    (32 MB)
__device__ float g_es[NN * 4];
__device__ float g_ed[NN * 4];
__device__ int   g_deg[NN];
__device__ int   g_rowptr[NN + 1];
__device__ int   g_cursor[NN];
__device__ int   g_csr[EE];
__device__ float g_dis[NN];
__device__ float g_bnsum[2048];       // layers at offsets 0,512,1024,1536
__device__ float g_bnsq[2048];
__device__ float g_wa[1024];          // [sel(2)][head(4)][k(128)]
__device__ float g_pooled[GG * 1024];
__device__ int   g_gstart[GG + 1];

// ---------------- fused setup: zero + wa projection + gstart ----------------
__global__ void k_setup(const float* __restrict__ gat_w,
                        const float* __restrict__ asrc, const float* __restrict__ adst,
                        const int* __restrict__ batch)
{
    int b = blockIdx.x;
    int tid = threadIdx.x;
    if (b < 64) {
        int i = b * 256 + tid;
        g_deg[i] = 0;
        g_cursor[i] = 0;
        if (i < 2048) { g_bnsum[i] = 0.f; g_bnsq[i] = 0.f; }
    } else if (b < 68) {
        int sub = (b - 64) * 2 + (tid >> 7);   // 0..7
        int k = tid & 127;
        int sel = sub >> 2, h = sub & 3;
        const float* a = (sel == 0) ? asrc : adst;
        float s = 0.f;
        for (int c = 0; c < 256; c++)
            s += gat_w[(size_t)k * 1024 + h * 256 + c] * a[h * 256 + c];
        g_wa[sel * 512 + h * 128 + k] = s;
    } else {
        int g = tid;
        if (g <= GG) {
            int lo = 0, hi = NN;
            while (lo < hi) {
                int mid = (lo + hi) >> 1;
                if (batch[mid] < g) lo = mid + 1;
                else hi = mid;
            }
            g_gstart[g] = lo;
        }
    }
}

__global__ void k_deg(const int* __restrict__ dst) {
    int e = blockIdx.x * blockDim.x + threadIdx.x;
    if (e < EE) atomicAdd(&g_deg[dst[e]], 1);
}

__global__ void k_scan() {
    __shared__ int sh[1024];
    int tid = threadIdx.x;
    int base = tid * 16;
    int s = 0;
    for (int i = 0; i < 16; i++) s += g_deg[base + i];
    sh[tid] = s;
    __syncthreads();
    for (int off = 1; off < 1024; off <<= 1) {
        int v = (tid >= off) ? sh[tid - off] : 0;
        __syncthreads();
        sh[tid] += v;
        __syncthreads();
    }
    int run = sh[tid] - s;
    for (int i = 0; i < 16; i++) {
        int dg = g_deg[base + i];
        g_rowptr[base + i] = run;
        g_dis[base + i] = rsqrtf((float)dg + 1.0f);
        run += dg;
    }
    if (tid == 1023) g_rowptr[NN] = sh[1023];
}

__global__ void k_csr_fill(const int* __restrict__ src, const int* __restrict__ dst) {
    int e = blockIdx.x * blockDim.x + threadIdx.x;
    if (e < EE) {
        int d = dst[e];
        int pos = g_rowptr[d] + atomicAdd(&g_cursor[d], 1);
        g_csr[pos] = src[e];
    }
}

// ---------------- layer 1 fully fused: gather(5ch) + 5x64 GEMV + BN stats ---
__global__ __launch_bounds__(256) void k_l1(const float* __restrict__ x,
                                            const float* __restrict__ W,
                                            float* __restrict__ C)
{
    __shared__ float sW[320];
    __shared__ float ssum[64], ssq[64];
    int tid = threadIdx.x;
    for (int t = tid; t < 320; t += 256) sW[t] = W[t];
    if (tid < 64) { ssum[tid] = 0.f; ssq[tid] = 0.f; }
    __syncthreads();

    int w = tid >> 5, lane = tid & 31;
    int d = blockIdx.x * 8 + w;
    int st = g_rowptr[d], deg = g_rowptr[d + 1] - st;
    float disd = g_dis[d];
    float a = 0.f;
    for (int i = 0; i < deg; i++) {
        int s = g_csr[st + i];
        float wt = g_dis[s];
        if (lane < 5) a += x[s * 5 + lane] * wt;
    }
    if (lane < 5) a = (a + x[d * 5 + lane] * disd) * disd;
    float xa0 = __shfl_sync(0xffffffffu, a, 0);
    float xa1 = __shfl_sync(0xffffffffu, a, 1);
    float xa2 = __shfl_sync(0xffffffffu, a, 2);
    float xa3 = __shfl_sync(0xffffffffu, a, 3);
    float xa4 = __shfl_sync(0xffffffffu, a, 4);

    int c0 = lane, c1 = lane + 32;
    float h0 = xa0 * sW[c0] + xa1 * sW[64 + c0] + xa2 * sW[128 + c0]
             + xa3 * sW[192 + c0] + xa4 * sW[256 + c0];
    float h1 = xa0 * sW[c1] + xa1 * sW[64 + c1] + xa2 * sW[128 + c1]
             + xa3 * sW[192 + c1] + xa4 * sW[256 + c1];
    C[(size_t)d * 64 + c0] = h0;
    C[(size_t)d * 64 + c1] = h1;
    atomicAdd(&ssum[c0], h0); atomicAdd(&ssq[c0], h0 * h0);
    atomicAdd(&ssum[c1], h1); atomicAdd(&ssq[c1], h1 * h1);
    __syncthreads();
    if (tid < 64) {
        atomicAdd(&g_bnsum[tid], ssum[tid]);
        atomicAdd(&g_bnsq[tid], ssq[tid]);
    }
}

// ---------------- SAGE aggregation with fused BN1+ReLU ----------------------
// Reads pre-BN C1 [N,64]; writes packed P[N,128]: cols 0..63 = mean-agg of
// BN1(neighbors), cols 64..127 = BN1(own row). Deletes the bn_apply pass.
__global__ __launch_bounds__(256) void k_sage_agg_bn(
    const float* __restrict__ C1,
    const float* __restrict__ gam, const float* __restrict__ bet,
    float* __restrict__ P)
{
    int w = threadIdx.x >> 5;
    int d = blockIdx.x * 8 + w;
    int lane = threadIdx.x & 31;
    int st = g_rowptr[d], deg = g_rowptr[d + 1] - st;
    int half = lane >> 4;
    int q = lane & 15;             // float4 chunk of 64 ch
    float sc[4], sh[4];
    float inv_n = 1.0f / (float)NN;
#pragma unroll
    for (int j = 0; j < 4; j++) {
        int c = q * 4 + j;
        float mean = g_bnsum[c] * inv_n;
        float var = g_bnsq[c] * inv_n - mean * mean;
        float s = rsqrtf(var + BN_EPS) * gam[c];
        sc[j] = s;
        sh[j] = bet[c] - mean * s;
    }
    const float4* C4 = (const float4*)C1;   // row stride 16
    float4 a = make_float4(0.f, 0.f, 0.f, 0.f);
    for (int i = 0; i < deg; i += 2) {
        int idx = i + half;
        if (idx < deg) {
            int s = g_csr[st + idx];
            float4 v = C4[(size_t)s * 16 + q];
            a.x += fmaxf(fmaf(v.x, sc[0], sh[0]), 0.f);
            a.y += fmaxf(fmaf(v.y, sc[1], sh[1]), 0.f);
            a.z += fmaxf(fmaf(v.z, sc[2], sh[2]), 0.f);
            a.w += fmaxf(fmaf(v.w, sc[3], sh[3]), 0.f);
        }
    }
    a.x += __shfl_xor_sync(0xffffffffu, a.x, 16);
    a.y += __shfl_xor_sync(0xffffffffu, a.y, 16);
    a.z += __shfl_xor_sync(0xffffffffu, a.z, 16);
    a.w += __shfl_xor_sync(0xffffffffu, a.w, 16);
    // own row BN (all lanes compute; lanes 0..15 write)
    float4 vd = C4[(size_t)d * 16 + q];
    float4 hd;
    hd.x = fmaxf(fmaf(vd.x, sc[0], sh[0]), 0.f);
    hd.y = fmaxf(fmaf(vd.y, sc[1], sh[1]), 0.f);
    hd.z = fmaxf(fmaf(vd.z, sc[2], sh[2]), 0.f);
    hd.w = fmaxf(fmaf(vd.w, sc[3], sh[3]), 0.f);
    if (lane < 16) {
        float inv = 1.f / (float)max(deg, 1);
        float4* P4 = (float4*)P;
        P4[(size_t)d * 32 + q] = make_float4(a.x * inv, a.y * inv, a.z * inv, a.w * inv);
        P4[(size_t)d * 32 + 16 + q] = hd;
    }
}

// ---------------- FP16 tensor-core GEMM, BK=32 + fused BN-stat epilogue -----
__device__ __forceinline__ void st_half4(__half* p, float4 v) {
    ((__half2*)p)[0] = __floats2half2_rn(v.x, v.y);
    ((__half2*)p)[1] = __floats2half2_rn(v.z, v.w);
}

__global__ __launch_bounds__(256, 2) void k_gemm_f16(
    const float* __restrict__ A,
    const float* __restrict__ W1, const float* __restrict__ W2, int ksplit,
    float* __restrict__ C, int M, int K, int Nn, int gatmode, int statoff)
{
    __shared__ __half As[128][40];   // 32 k + pad (stride 40 halfs)
    __shared__ __half Bs[32][136];   // 128 cols + pad
    __shared__ float red[2][128][2];

    int tid = threadIdx.x;
    int warp = tid >> 5;
    int wm = warp >> 2;              // 0..1
    int wn = warp & 3;               // 0..3
    int row0 = blockIdx.y * 128, col0 = blockIdx.x * 128;

    // A slots: 4 float4/thread covering 128 rows x 8 float4 (32 k)
    int a_r[4], a_c[4];
#pragma unroll
    for (int i = 0; i < 4; i++) {
        int s = tid * 4 + i;
        a_r[i] = s >> 3;
        a_c[i] = (s & 7) * 4;
    }
    // B slots: 4 float4/thread covering 32 k-rows x 32 float4 (128 cols)
    int b_r[4], b_c[4];
#pragma unroll
    for (int i = 0; i < 4; i++) {
        int s = tid + 256 * i;
        b_r[i] = s >> 5;
        b_c[i] = (s & 31) * 4;
    }

    const float* Abase = A + (size_t)row0 * K;

    float4 cA[4], cB[4];
#pragma unroll
    for (int i = 0; i < 4; i++) {
        cA[i] = *(const float4*)(Abase + (size_t)a_r[i] * K + a_c[i]);
        int k = b_r[i];
        const float* wp;
        if (gatmode) wp = W1 + (size_t)(k & 127) * 1024 + (k >> 7) * 256;
        else wp = (k < ksplit) ? (W1 + (size_t)k * Nn)
                               : (W2 + (size_t)(k - ksplit) * Nn);
        cB[i] = *(const float4*)(wp + col0 + b_c[i]);
    }

    wmma::fragment<wmma::accumulator, 16, 16, 16, float> acc[4][2];
#pragma unroll
    for (int i = 0; i < 4; i++)
#pragma unroll
        for (int j = 0; j < 2; j++) wmma::fill_fragment(acc[i][j], 0.f);

    for (int k0 = 0; k0 < K; k0 += 32) {
#pragma unroll
        for (int i = 0; i < 4; i++) {
            st_half4(&As[a_r[i]][a_c[i]], cA[i]);
            st_half4(&Bs[b_r[i]][b_c[i]], cB[i]);
        }
        __syncthreads();
        if (k0 + 32 < K) {
#pragma unroll
            for (int i = 0; i < 4; i++) {
                cA[i] = *(const float4*)(Abase + (size_t)a_r[i] * K + (k0 + 32) + a_c[i]);
                int k = k0 + 32 + b_r[i];
                const float* wp;
                if (gatmode) wp = W1 + (size_t)(k & 127) * 1024 + (k >> 7) * 256;
                else wp = (k < ksplit) ? (W1 + (size_t)k * Nn)
                                       : (W2 + (size_t)(k - ksplit) * Nn);
                cB[i] = *(const float4*)(wp + col0 + b_c[i]);
            }
        }
#pragma unroll
        for (int kk = 0; kk < 32; kk += 16) {
            wmma::fragment<wmma::matrix_a, 16, 16, 16, __half, wmma::row_major> af[4];
            wmma::fragment<wmma::matrix_b, 16, 16, 16, __half, wmma::row_major> bf[2];
#pragma unroll
            for (int i = 0; i < 4; i++)
                wmma::load_matrix_sync(af[i], &As[wm * 64 + i * 16][kk], 40);
#pragma unroll
            for (int j = 0; j < 2; j++)
                wmma::load_matrix_sync(bf[j], &Bs[kk][wn * 32 + j * 16], 136);
#pragma unroll
            for (int i = 0; i < 4; i++)
#pragma unroll
                for (int j = 0; j < 2; j++)
                    wmma::mma_sync(acc[i][j], af[i], bf[j], acc[i][j]);
        }
        __syncthreads();
    }

#pragma unroll
    for (int i = 0; i < 4; i++)
#pragma unroll
        for (int j = 0; j < 2; j++) {
            int gr = row0 + wm * 64 + i * 16;
            int gc = col0 + wn * 32 + j * 16;
            wmma::store_matrix_sync(C + (size_t)gr * Nn + gc, acc[i][j], Nn,
                                    wmma::mem_row_major);
        }

    // fused BN-stat epilogue: reduce this block's own (L2-hot) tile
    if (statoff >= 0) {
        __syncthreads();
        int c = tid & 127, rh = tid >> 7;
        const float* cp = C + (size_t)(row0 + rh * 64) * Nn + col0 + c;
        float s = 0.f, q = 0.f;
#pragma unroll 4
        for (int r = 0; r < 64; r++) {
            float v = cp[(size_t)r * Nn];
            s += v;
            q += v * v;
        }
        red[rh][c][0] = s;
        red[rh][c][1] = q;
        __syncthreads();
        if (rh == 0) {
            s += red[1][c][0];
            q += red[1][c][1];
            atomicAdd(&g_bnsum[statoff + col0 + c], s);
            atomicAdd(&g_bnsq[statoff + col0 + c], q);
        }
    }
}

// ---------------- layer-4 GCN gather with fused BN3+ReLU -------------------
__global__ __launch_bounds__(256) void k_gcn_agg4_bn(
    const float* __restrict__ C3,
    const float* __restrict__ gam, const float* __restrict__ bet,
    float* __restrict__ out)
{
    int tid = threadIdx.x;
    int d = blockIdx.x * 4 + (tid >> 6);
    int t = tid & 63;
    int st = g_rowptr[d], deg = g_rowptr[d + 1] - st;
    float disd = g_dis[d];
    float sc[4], sh[4];
    float inv_n = 1.0f / (float)NN;
#pragma unroll
    for (int j = 0; j < 4; j++) {
        int c = t * 4 + j;
        float mean = g_bnsum[1024 + c] * inv_n;
        float var = g_bnsq[1024 + c] * inv_n - mean * mean;
        float s = rsqrtf(var + BN_EPS) * gam[c];
        sc[j] = s;
        sh[j] = bet[c] - mean * s;
    }
    const float4* in4 = (const float4*)C3;
    float4 a = make_float4(0.f, 0.f, 0.f, 0.f);
    int i = 0;
    for (; i + 2 <= deg; i += 2) {
        int s0 = g_csr[st + i], s1 = g_csr[st + i + 1];
        float w0 = g_dis[s0], w1 = g_dis[s1];
        float4 v0 = in4[(size_t)s0 * 64 + t];
        float4 v1 = in4[(size_t)s1 * 64 + t];
        a.x += fmaxf(fmaf(v0.x, sc[0], sh[0]), 0.f) * w0 + fmaxf(fmaf(v1.x, sc[0], sh[0]), 0.f) * w1;
        a.y += fmaxf(fmaf(v0.y, sc[1], sh[1]), 0.f) * w0 + fmaxf(fmaf(v1.y, sc[1], sh[1]), 0.f) * w1;
        a.z += fmaxf(fmaf(v0.z, sc[2], sh[2]), 0.f) * w0 + fmaxf(fmaf(v1.z, sc[2], sh[2]), 0.f) * w1;
        a.w += fmaxf(fmaf(v0.w, sc[3], sh[3]), 0.f) * w0 + fmaxf(fmaf(v1.w, sc[3], sh[3]), 0.f) * w1;
    }
    if (i < deg) {
        int s0 = g_csr[st + i];
        float w0 = g_dis[s0];
        float4 v0 = in4[(size_t)s0 * 64 + t];
        a.x += fmaxf(fmaf(v0.x, sc[0], sh[0]), 0.f) * w0;
        a.y += fmaxf(fmaf(v0.y, sc[1], sh[1]), 0.f) * w0;
        a.z += fmaxf(fmaf(v0.z, sc[2], sh[2]), 0.f) * w0;
        a.w += fmaxf(fmaf(v0.w, sc[3], sh[3]), 0.f) * w0;
    }
    float4 v = in4[(size_t)d * 64 + t];
    a.x += fmaxf(fmaf(v.x, sc[0], sh[0]), 0.f) * disd;
    a.y += fmaxf(fmaf(v.y, sc[1], sh[1]), 0.f) * disd;
    a.z += fmaxf(fmaf(v.z, sc[2], sh[2]), 0.f) * disd;
    a.w += fmaxf(fmaf(v.w, sc[3], sh[3]), 0.f) * disd;
    a.x *= disd; a.y *= disd; a.z *= disd; a.w *= disd;
    ((float4*)out)[(size_t)d * 64 + t] = a;
}

// ---------------- BN2 apply + es/ed fused ------------------------------------
__global__ __launch_bounds__(256) void k_bn2_esed(
    const float* __restrict__ C2, const float* __restrict__ gam,
    const float* __restrict__ bet, float* __restrict__ D)
{
    __shared__ float swa[1024];
    int tid = threadIdx.x;
    for (int t = tid; t < 1024; t += 256) swa[t] = g_wa[t];
    __syncthreads();
    int w = tid >> 5, lane = tid & 31;
    int n = blockIdx.x * 8 + w;
    float4 v = ((const float4*)C2)[(size_t)n * 32 + lane];
    float inv_n = 1.0f / (float)NN;
    float r[4] = {v.x, v.y, v.z, v.w};
#pragma unroll
    for (int j = 0; j < 4; j++) {
        int c = lane * 4 + j;
        float mean = g_bnsum[512 + c] * inv_n;
        float var = g_bnsq[512 + c] * inv_n - mean * mean;
        float y = (r[j] - mean) * rsqrtf(var + BN_EPS) * gam[c] + bet[c];
        r[j] = fmaxf(y, 0.f);
    }
    ((float4*)D)[(size_t)n * 32 + lane] = make_float4(r[0], r[1], r[2], r[3]);

    float p[8];
#pragma unroll
    for (int s = 0; s < 2; s++)
#pragma unroll
        for (int h = 0; h < 4; h++) {
            float4 wv = ((const float4*)swa)[(s * 512 + h * 128) / 4 + lane];
            p[s * 4 + h] = r[0] * wv.x + r[1] * wv.y + r[2] * wv.z + r[3] * wv.w;
        }
#pragma unroll
    for (int o = 16; o > 0; o >>= 1)
#pragma unroll
        for (int j = 0; j < 8; j++)
            p[j] += __shfl_xor_sync(0xffffffffu, p[j], o);
    if (lane < 4) g_es[n * 4 + lane] = p[lane];
    else if (lane < 8) g_ed[n * 4 + (lane - 4)] = p[lane];
}

__device__ __forceinline__ float leaky02(float x) { return x > 0.f ? x : 0.2f * x; }

// ---------------- warp-autonomous GAT aggregation ----------------------------
__global__ __launch_bounds__(256) void k_gat_agg(const float* __restrict__ D,
                                                 float* __restrict__ agg)
{
    int warp = threadIdx.x >> 5;
    int lane = threadIdx.x & 31;
    int d = blockIdx.x * 2 + (warp >> 2);
    int h = warp & 3;
    int st = g_rowptr[d], deg = g_rowptr[d + 1] - st;
    float edv = g_ed[d * 4 + h];
    float eself = leaky02(g_es[d * 4 + h] + edv);

    float m = eself;
    for (int i = lane; i < deg; i += 32)
        m = fmaxf(m, leaky02(g_es[g_csr[st + i] * 4 + h] + edv));
#pragma unroll
    for (int o = 16; o > 0; o >>= 1) m = fmaxf(m, __shfl_xor_sync(0xffffffffu, m, o));
    float z = (lane == 0) ? __expf(eself - m) : 0.f;
    for (int i = lane; i < deg; i += 32)
        z += __expf(leaky02(g_es[g_csr[st + i] * 4 + h] + edv) - m);
#pragma unroll
    for (int o = 16; o > 0; o >>= 1) z += __shfl_xor_sync(0xffffffffu, z, o);
    float invz = 1.f / z;

    const float4* D4 = (const float4*)D;
    float4 acc = make_float4(0.f, 0.f, 0.f, 0.f);
    int i = 0;
    for (; i + 2 <= deg; i += 2) {
        int s0 = g_csr[st + i], s1 = g_csr[st + i + 1];
        float a0 = __expf(leaky02(g_es[s0 * 4 + h] + edv) - m) * invz;
        float a1 = __expf(leaky02(g_es[s1 * 4 + h] + edv) - m) * invz;
        float4 v0 = D4[(size_t)s0 * 32 + lane];
        float4 v1 = D4[(size_t)s1 * 32 + lane];
        acc.x += v0.x * a0 + v1.x * a1;
        acc.y += v0.y * a0 + v1.y * a1;
        acc.z += v0.z * a0 + v1.z * a1;
        acc.w += v0.w * a0 + v1.w * a1;
    }
    if (i < deg) {
        int s0 = g_csr[st + i];
        float a0 = __expf(leaky02(g_es[s0 * 4 + h] + edv) - m) * invz;
        float4 v0 = D4[(size_t)s0 * 32 + lane];
        acc.x += v0.x * a0; acc.y += v0.y * a0; acc.z += v0.z * a0; acc.w += v0.w * a0;
    }
    {
        float a0 = __expf(eself - m) * invz;
        float4 v0 = D4[(size_t)d * 32 + lane];
        acc.x += v0.x * a0; acc.y += v0.y * a0; acc.z += v0.z * a0; acc.w += v0.w * a0;
    }
    ((float4*)agg)[(size_t)d * 128 + h * 32 + lane] = acc;
}

// ---------------- pooling (fused BN4+ReLU) + FC -----------------------------
__global__ void k_pool_bn(const float* __restrict__ C4buf,
                          const float* __restrict__ gam, const float* __restrict__ bet)
{
    int g = blockIdx.x;
    int c4 = threadIdx.x;  // 128
    int st = g_gstart[g], en = g_gstart[g + 1];
    int cnt = en - st;
    float sc[4], sh[4];
    float inv_n = 1.0f / (float)NN;
#pragma unroll
    for (int j = 0; j < 4; j++) {
        int c = c4 * 4 + j;
        float mean = g_bnsum[1536 + c] * inv_n;
        float var = g_bnsq[1536 + c] * inv_n - mean * mean;
        float s = rsqrtf(var + BN_EPS) * gam[c];
        sc[j] = s;
        sh[j] = bet[c] - mean * s;
    }
    const float4* D4 = (const float4*)C4buf;
    float4 s = make_float4(0.f, 0.f, 0.f, 0.f);
    float4 m = make_float4(-3.4e38f, -3.4e38f, -3.4e38f, -3.4e38f);
    for (int i = st; i < en; i++) {
        float4 v = D4[(size_t)i * 128 + c4];
        v.x = fmaxf(fmaf(v.x, sc[0], sh[0]), 0.f);
        v.y = fmaxf(fmaf(v.y, sc[1], sh[1]), 0.f);
        v.z = fmaxf(fmaf(v.z, sc[2], sh[2]), 0.f);
        v.w = fmaxf(fmaf(v.w, sc[3], sh[3]), 0.f);
        s.x += v.x; s.y += v.y; s.z += v.z; s.w += v.w;
        m.x = fmaxf(m.x, v.x); m.y = fmaxf(m.y, v.y);
        m.z = fmaxf(m.z, v.z); m.w = fmaxf(m.w, v.w);
    }
    float inv = 1.f / (float)max(cnt, 1);
    float4* P4 = (float4*)g_pooled;
    P4[g * 256 + c4] = make_float4(s.x * inv, s.y * inv, s.z * inv, s.w * inv);
    if (cnt <= 0) m = make_float4(0.f, 0.f, 0.f, 0.f);
    P4[g * 256 + 128 + c4] = m;
}

__global__ __launch_bounds__(128) void k_fc(const float* __restrict__ W,
                                            const float* __restrict__ bias,
                                            float* __restrict__ out)
{
    __shared__ float sp[4][1024];
    int tid = threadIdx.x;
    int j = blockIdx.x * 128 + tid;
    int g0 = blockIdx.y * 4;
    for (int t = tid; t < 4 * 1024; t += 128)
        sp[t >> 10][t & 1023] = g_pooled[(g0 + (t >> 10)) * 1024 + (t & 1023)];
    __syncthreads();
    float acc[4] = {0.f, 0.f, 0.f, 0.f};
#pragma unroll 4
    for (int kk = 0; kk < 1024; kk++) {
        float wv = W[(size_t)kk * 1024 + j];
#pragma unroll
        for (int g = 0; g < 4; g++) acc[g] += sp[g][kk] * wv;
    }
    float bv = bias[j];
#pragma unroll
    for (int g = 0; g < 4; g++) out[(size_t)(g0 + g) * 1024 + j] = acc[g] + bv;
}

// ---------------- host orchestration ---------------------------------------
extern "C" void kernel_launch(void* const* d_in, const int* in_sizes, int n_in,
                              void* d_out, int out_size)
{
    const float* x        = (const float*)d_in[0];
    const int*   ei       = (const int*)  d_in[1];
    const int*   batch    = (const int*)  d_in[2];
    const float* gcn1_w   = (const float*)d_in[3];
    const float* sage_wl  = (const float*)d_in[5];
    const float* sage_wr  = (const float*)d_in[6];
    const float* gat_w    = (const float*)d_in[8];
    const float* gat_asrc = (const float*)d_in[9];
    const float* gat_adst = (const float*)d_in[10];
    const float* gcn4_w   = (const float*)d_in[12];
    const float* bn1_g = (const float*)d_in[14]; const float* bn1_b = (const float*)d_in[15];
    const float* bn2_g = (const float*)d_in[16]; const float* bn2_b = (const float*)d_in[17];
    const float* bn3_g = (const float*)d_in[18]; const float* bn3_b = (const float*)d_in[19];
    const float* bn4_g = (const float*)d_in[20]; const float* bn4_b = (const float*)d_in[21];
    const float* fc_w  = (const float*)d_in[22]; const float* fc_b  = (const float*)d_in[23];
    float* out = (float*)d_out;

    const int* src = ei;
    const int* dst = ei + EE;

    float *A, *B, *C, *D;
    cudaGetSymbolAddress((void**)&A, g_bufA);
    cudaGetSymbolAddress((void**)&B, g_bufB);
    cudaGetSymbolAddress((void**)&C, g_bufC);
    cudaGetSymbolAddress((void**)&D, g_bufD);

    // setup (zero + wa + gstart) and graph build
    k_setup<<<69, 256>>>(gat_w, gat_asrc, gat_adst, batch);
    k_deg<<<EE / 256, 256>>>(dst);
    k_scan<<<1, 1024>>>();
    k_csr_fill<<<EE / 256, 256>>>(src, dst);

    // ---- layer 1: fused gather + GEMV + BN stats ----
    k_l1<<<NN / 8, 256>>>(x, gcn1_w, C);

    // ---- layer 2: SAGE(64->128) with fused BN1; single GEMM + stats ----
    k_sage_agg_bn<<<NN / 8, 256>>>(C, bn1_g, bn1_b, B);
    k_gemm_f16<<<dim3(1, NN / 128), 256>>>(B, sage_wl, sage_wr, 64, C, NN, 128, 128, 0, 512);
    k_bn2_esed<<<NN / 8, 256>>>(C, bn2_g, bn2_b, D);

    // ---- layer 3: GAT aggregate-then-transform + stats ----
    k_gat_agg<<<NN / 2, 256>>>(D, A);
    k_gemm_f16<<<dim3(2, NN / 128), 256>>>(A, gat_w, nullptr, 0, C, NN, 512, 256, 1, 1024);

    // ---- layer 4: GCN with fused BN3 gather, GEMM + stats ----
    k_gcn_agg4_bn<<<NN / 4, 256>>>(C, bn3_g, bn3_b, B);
    k_gemm_f16<<<dim3(4, NN / 128), 256>>>(B, gcn4_w, gcn4_w, 256, C, NN, 256, 512, 0, 1536);

    // ---- pooling (BN4 fused) + FC ----
    k_pool_bn<<<GG, 128>>>(C, bn4_g, bn4_b);
    k_fc<<<dim3(8, 8), 128>>>(fc_w, fc_b, out);
}

// round 13
// speedup vs baseline: 1.1792x; 1.1792x over previous
#include <cuda_runtime.h>
#include <cuda_fp16.h>
#include <mma.h>
#include <math.h>

using namespace nvcuda;

#define NN 16384
#define EE 131072
#define GG 32
#define BN_EPS 1e-5f

// ---------------- scratch (device globals: no allocation allowed) ----------
__device__ float g_bufA[NN * 512];    // GAT per-head agg [N,512] (32 MB)
__device__ float g_bufB[NN * 512];    // packed sage / agg        (32 MB)
__device__ float g_bufC[NN * 512];    // pre-BN buffers           (32 MB)
__device__ float g_bufD[NN * 512];    // post-BN layer2 output    (32 MB)
__device__ float g_es[NN * 4];
__device__ float g_ed[NN * 4];
__device__ int   g_deg[NN];
__device__ int   g_rowptr[NN + 1];
__device__ int   g_cursor[NN];
__device__ int   g_csr[EE];
__device__ float g_dis[NN];
__device__ float g_bnsum[2048];       // layers at offsets 0,512,1024,1536
__device__ float g_bnsq[2048];
__device__ float g_wa[1024];          // [sel(2)][head(4)][k(128)]
__device__ float g_pooled[GG * 1024]; // [g][0:512]=sum, [512:1024]=max (atomics)
__device__ int   g_gstart[GG + 1];

// ---------------- fused setup: zero + wa projection + gstart ----------------
__global__ void k_setup(const float* __restrict__ gat_w,
                        const float* __restrict__ asrc, const float* __restrict__ adst,
                        const int* __restrict__ batch)
{
    int b = blockIdx.x;
    int tid = threadIdx.x;
    if (b < 64) {
        int i = b * 256 + tid;
        g_deg[i] = 0;
        g_cursor[i] = 0;
        if (i < 2048) { g_bnsum[i] = 0.f; g_bnsq[i] = 0.f; }
        g_pooled[i] = 0.f;
        g_pooled[i + 16384] = 0.f;
    } else if (b < 68) {
        int sub = (b - 64) * 2 + (tid >> 7);   // 0..7
        int k = tid & 127;
        int sel = sub >> 2, h = sub & 3;
        const float* a = (sel == 0) ? asrc : adst;
        float s = 0.f;
        for (int c = 0; c < 256; c++)
            s += gat_w[(size_t)k * 1024 + h * 256 + c] * a[h * 256 + c];
        g_wa[sel * 512 + h * 128 + k] = s;
    } else {
        int g = tid;
        if (g <= GG) {
            int lo = 0, hi = NN;
            while (lo < hi) {
                int mid = (lo + hi) >> 1;
                if (batch[mid] < g) lo = mid + 1;
                else hi = mid;
            }
            g_gstart[g] = lo;
        }
    }
}

__global__ void k_deg(const int* __restrict__ dst) {
    int e = blockIdx.x * blockDim.x + threadIdx.x;
    if (e < EE) atomicAdd(&g_deg[dst[e]], 1);
}

__global__ void k_scan() {
    __shared__ int sh[1024];
    int tid = threadIdx.x;
    int base = tid * 16;
    int s = 0;
    for (int i = 0; i < 16; i++) s += g_deg[base + i];
    sh[tid] = s;
    __syncthreads();
    for (int off = 1; off < 1024; off <<= 1) {
        int v = (tid >= off) ? sh[tid - off] : 0;
        __syncthreads();
        sh[tid] += v;
        __syncthreads();
    }
    int run = sh[tid] - s;
    for (int i = 0; i < 16; i++) {
        int dg = g_deg[base + i];
        g_rowptr[base + i] = run;
        g_dis[base + i] = rsqrtf((float)dg + 1.0f);
        run += dg;
    }
    if (tid == 1023) g_rowptr[NN] = sh[1023];
}

__global__ void k_csr_fill(const int* __restrict__ src, const int* __restrict__ dst) {
    int e = blockIdx.x * blockDim.x + threadIdx.x;
    if (e < EE) {
        int d = dst[e];
        int pos = g_rowptr[d] + atomicAdd(&g_cursor[d], 1);
        g_csr[pos] = src[e];
    }
}

// ---------------- layer 1 fully fused: gather(5ch) + 5x64 GEMV + BN stats ---
__global__ __launch_bounds__(256) void k_l1(const float* __restrict__ x,
                                            const float* __restrict__ W,
                                            float* __restrict__ C)
{
    __shared__ float sW[320];
    __shared__ float ssum[64], ssq[64];
    int tid = threadIdx.x;
    for (int t = tid; t < 320; t += 256) sW[t] = W[t];
    if (tid < 64) { ssum[tid] = 0.f; ssq[tid] = 0.f; }
    __syncthreads();

    int w = tid >> 5, lane = tid & 31;
    int d = blockIdx.x * 8 + w;
    int st = g_rowptr[d], deg = g_rowptr[d + 1] - st;
    float disd = g_dis[d];
    float a = 0.f;
    for (int i = 0; i < deg; i++) {
        int s = g_csr[st + i];
        float wt = g_dis[s];
        if (lane < 5) a += x[s * 5 + lane] * wt;
    }
    if (lane < 5) a = (a + x[d * 5 + lane] * disd) * disd;
    float xa0 = __shfl_sync(0xffffffffu, a, 0);
    float xa1 = __shfl_sync(0xffffffffu, a, 1);
    float xa2 = __shfl_sync(0xffffffffu, a, 2);
    float xa3 = __shfl_sync(0xffffffffu, a, 3);
    float xa4 = __shfl_sync(0xffffffffu, a, 4);

    int c0 = lane, c1 = lane + 32;
    float h0 = xa0 * sW[c0] + xa1 * sW[64 + c0] + xa2 * sW[128 + c0]
             + xa3 * sW[192 + c0] + xa4 * sW[256 + c0];
    float h1 = xa0 * sW[c1] + xa1 * sW[64 + c1] + xa2 * sW[128 + c1]
             + xa3 * sW[192 + c1] + xa4 * sW[256 + c1];
    C[(size_t)d * 64 + c0] = h0;
    C[(size_t)d * 64 + c1] = h1;
    atomicAdd(&ssum[c0], h0); atomicAdd(&ssq[c0], h0 * h0);
    atomicAdd(&ssum[c1], h1); atomicAdd(&ssq[c1], h1 * h1);
    __syncthreads();
    if (tid < 64) {
        atomicAdd(&g_bnsum[tid], ssum[tid]);
        atomicAdd(&g_bnsq[tid], ssq[tid]);
    }
}

// ---------------- SAGE aggregation with fused BN1+ReLU ----------------------
__global__ __launch_bounds__(256) void k_sage_agg_bn(
    const float* __restrict__ C1,
    const float* __restrict__ gam, const float* __restrict__ bet,
    float* __restrict__ P)
{
    int w = threadIdx.x >> 5;
    int d = blockIdx.x * 8 + w;
    int lane = threadIdx.x & 31;
    int st = g_rowptr[d], deg = g_rowptr[d + 1] - st;
    int half = lane >> 4;
    int q = lane & 15;             // float4 chunk of 64 ch
    float sc[4], sh[4];
    float inv_n = 1.0f / (float)NN;
#pragma unroll
    for (int j = 0; j < 4; j++) {
        int c = q * 4 + j;
        float mean = g_bnsum[c] * inv_n;
        float var = g_bnsq[c] * inv_n - mean * mean;
        float s = rsqrtf(var + BN_EPS) * gam[c];
        sc[j] = s;
        sh[j] = bet[c] - mean * s;
    }
    const float4* C4 = (const float4*)C1;   // row stride 16
    float4 a = make_float4(0.f, 0.f, 0.f, 0.f);
    for (int i = 0; i < deg; i += 2) {
        int idx = i + half;
        if (idx < deg) {
            int s = g_csr[st + idx];
            float4 v = C4[(size_t)s * 16 + q];
            a.x += fmaxf(fmaf(v.x, sc[0], sh[0]), 0.f);
            a.y += fmaxf(fmaf(v.y, sc[1], sh[1]), 0.f);
            a.z += fmaxf(fmaf(v.z, sc[2], sh[2]), 0.f);
            a.w += fmaxf(fmaf(v.w, sc[3], sh[3]), 0.f);
        }
    }
    a.x += __shfl_xor_sync(0xffffffffu, a.x, 16);
    a.y += __shfl_xor_sync(0xffffffffu, a.y, 16);
    a.z += __shfl_xor_sync(0xffffffffu, a.z, 16);
    a.w += __shfl_xor_sync(0xffffffffu, a.w, 16);
    float4 vd = C4[(size_t)d * 16 + q];
    float4 hd;
    hd.x = fmaxf(fmaf(vd.x, sc[0], sh[0]), 0.f);
    hd.y = fmaxf(fmaf(vd.y, sc[1], sh[1]), 0.f);
    hd.z = fmaxf(fmaf(vd.z, sc[2], sh[2]), 0.f);
    hd.w = fmaxf(fmaf(vd.w, sc[3], sh[3]), 0.f);
    if (lane < 16) {
        float inv = 1.f / (float)max(deg, 1);
        float4* P4 = (float4*)P;
        P4[(size_t)d * 32 + q] = make_float4(a.x * inv, a.y * inv, a.z * inv, a.w * inv);
        P4[(size_t)d * 32 + 16 + q] = hd;
    }
}

// ---------------- FP16 tensor-core GEMM (BK=16) + fused BN-stat epilogue ----
__device__ __forceinline__ void st_half4(__half* p, float4 v) {
    ((__half2*)p)[0] = __floats2half2_rn(v.x, v.y);
    ((__half2*)p)[1] = __floats2half2_rn(v.z, v.w);
}

__global__ __launch_bounds__(256, 2) void k_gemm_f16(
    const float* __restrict__ A,
    const float* __restrict__ W1, const float* __restrict__ W2, int ksplit,
    float* __restrict__ C, int M, int K, int Nn, int gatmode, int statoff)
{
    __shared__ __half As[128][24];
    __shared__ __half Bs[16][136];
    __shared__ float red[2][128][2];

    int tid = threadIdx.x;
    int warp = tid >> 5;
    int wm = warp >> 2;
    int wn = warp & 3;
    int row0 = blockIdx.y * 128, col0 = blockIdx.x * 128;

    int a_r[2], a_c[2];
#pragma unroll
    for (int i = 0; i < 2; i++) {
        int s = tid * 2 + i;
        a_r[i] = s >> 2;
        a_c[i] = (s & 3) * 4;
    }
    int b_r[2], b_c[2];
#pragma unroll
    for (int i = 0; i < 2; i++) {
        int s = tid + 256 * i;
        b_r[i] = s >> 5;
        b_c[i] = (s & 31) * 4;
    }

    const float* Abase = A + (size_t)row0 * K;

    float4 cA[2], cB[2];
#pragma unroll
    for (int i = 0; i < 2; i++) {
        cA[i] = *(const float4*)(Abase + (size_t)a_r[i] * K + a_c[i]);
        int k = b_r[i];
        const float* wp;
        if (gatmode) wp = W1 + (size_t)(k & 127) * 1024 + (k >> 7) * 256;
        else wp = (k < ksplit) ? (W1 + (size_t)k * Nn)
                               : (W2 + (size_t)(k - ksplit) * Nn);
        cB[i] = *(const float4*)(wp + col0 + b_c[i]);
    }

    wmma::fragment<wmma::accumulator, 16, 16, 16, float> acc[4][2];
#pragma unroll
    for (int i = 0; i < 4; i++)
#pragma unroll
        for (int j = 0; j < 2; j++) wmma::fill_fragment(acc[i][j], 0.f);

    for (int k0 = 0; k0 < K; k0 += 16) {
#pragma unroll
        for (int i = 0; i < 2; i++) {
            st_half4(&As[a_r[i]][a_c[i]], cA[i]);
            st_half4(&Bs[b_r[i]][b_c[i]], cB[i]);
        }
        __syncthreads();
        if (k0 + 16 < K) {
#pragma unroll
            for (int i = 0; i < 2; i++) {
                cA[i] = *(const float4*)(Abase + (size_t)a_r[i] * K + (k0 + 16) + a_c[i]);
                int k = k0 + 16 + b_r[i];
                const float* wp;
                if (gatmode) wp = W1 + (size_t)(k & 127) * 1024 + (k >> 7) * 256;
                else wp = (k < ksplit) ? (W1 + (size_t)k * Nn)
                                       : (W2 + (size_t)(k - ksplit) * Nn);
                cB[i] = *(const float4*)(wp + col0 + b_c[i]);
            }
        }
        {
            wmma::fragment<wmma::matrix_a, 16, 16, 16, __half, wmma::row_major> af[4];
            wmma::fragment<wmma::matrix_b, 16, 16, 16, __half, wmma::row_major> bf[2];
#pragma unroll
            for (int i = 0; i < 4; i++)
                wmma::load_matrix_sync(af[i], &As[wm * 64 + i * 16][0], 24);
#pragma unroll
            for (int j = 0; j < 2; j++)
                wmma::load_matrix_sync(bf[j], &Bs[0][wn * 32 + j * 16], 136);
#pragma unroll
            for (int i = 0; i < 4; i++)
#pragma unroll
                for (int j = 0; j < 2; j++)
                    wmma::mma_sync(acc[i][j], af[i], bf[j], acc[i][j]);
        }
        __syncthreads();
    }

#pragma unroll
    for (int i = 0; i < 4; i++)
#pragma unroll
        for (int j = 0; j < 2; j++) {
            int gr = row0 + wm * 64 + i * 16;
            int gc = col0 + wn * 32 + j * 16;
            wmma::store_matrix_sync(C + (size_t)gr * Nn + gc, acc[i][j], Nn,
                                    wmma::mem_row_major);
        }

    if (statoff >= 0) {
        __syncthreads();
        int c = tid & 127, rh = tid >> 7;
        const float* cp = C + (size_t)(row0 + rh * 64) * Nn + col0 + c;
        float s = 0.f, q = 0.f;
#pragma unroll 4
        for (int r = 0; r < 64; r++) {
            float v = cp[(size_t)r * Nn];
            s += v;
            q += v * v;
        }
        red[rh][c][0] = s;
        red[rh][c][1] = q;
        __syncthreads();
        if (rh == 0) {
            s += red[1][c][0];
            q += red[1][c][1];
            atomicAdd(&g_bnsum[statoff + col0 + c], s);
            atomicAdd(&g_bnsq[statoff + col0 + c], q);
        }
    }
}

// ---------------- layer-4 GCN gather with fused BN3+ReLU -------------------
__global__ __launch_bounds__(256) void k_gcn_agg4_bn(
    const float* __restrict__ C3,
    const float* __restrict__ gam, const float* __restrict__ bet,
    float* __restrict__ out)
{
    int tid = threadIdx.x;
    int d = blockIdx.x * 4 + (tid >> 6);
    int t = tid & 63;
    int st = g_rowptr[d], deg = g_rowptr[d + 1] - st;
    float disd = g_dis[d];
    float sc[4], sh[4];
    float inv_n = 1.0f / (float)NN;
#pragma unroll
    for (int j = 0; j < 4; j++) {
        int c = t * 4 + j;
        float mean = g_bnsum[1024 + c] * inv_n;
        float var = g_bnsq[1024 + c] * inv_n - mean * mean;
        float s = rsqrtf(var + BN_EPS) * gam[c];
        sc[j] = s;
        sh[j] = bet[c] - mean * s;
    }
    const float4* in4 = (const float4*)C3;
    float4 a = make_float4(0.f, 0.f, 0.f, 0.f);
    int i = 0;
    for (; i + 2 <= deg; i += 2) {
        int s0 = g_csr[st + i], s1 = g_csr[st + i + 1];
        float w0 = g_dis[s0], w1 = g_dis[s1];
        float4 v0 = in4[(size_t)s0 * 64 + t];
        float4 v1 = in4[(size_t)s1 * 64 + t];
        a.x += fmaxf(fmaf(v0.x, sc[0], sh[0]), 0.f) * w0 + fmaxf(fmaf(v1.x, sc[0], sh[0]), 0.f) * w1;
        a.y += fmaxf(fmaf(v0.y, sc[1], sh[1]), 0.f) * w0 + fmaxf(fmaf(v1.y, sc[1], sh[1]), 0.f) * w1;
        a.z += fmaxf(fmaf(v0.z, sc[2], sh[2]), 0.f) * w0 + fmaxf(fmaf(v1.z, sc[2], sh[2]), 0.f) * w1;
        a.w += fmaxf(fmaf(v0.w, sc[3], sh[3]), 0.f) * w0 + fmaxf(fmaf(v1.w, sc[3], sh[3]), 0.f) * w1;
    }
    if (i < deg) {
        int s0 = g_csr[st + i];
        float w0 = g_dis[s0];
        float4 v0 = in4[(size_t)s0 * 64 + t];
        a.x += fmaxf(fmaf(v0.x, sc[0], sh[0]), 0.f) * w0;
        a.y += fmaxf(fmaf(v0.y, sc[1], sh[1]), 0.f) * w0;
        a.z += fmaxf(fmaf(v0.z, sc[2], sh[2]), 0.f) * w0;
        a.w += fmaxf(fmaf(v0.w, sc[3], sh[3]), 0.f) * w0;
    }
    float4 v = in4[(size_t)d * 64 + t];
    a.x += fmaxf(fmaf(v.x, sc[0], sh[0]), 0.f) * disd;
    a.y += fmaxf(fmaf(v.y, sc[1], sh[1]), 0.f) * disd;
    a.z += fmaxf(fmaf(v.z, sc[2], sh[2]), 0.f) * disd;
    a.w += fmaxf(fmaf(v.w, sc[3], sh[3]), 0.f) * disd;
    a.x *= disd; a.y *= disd; a.z *= disd; a.w *= disd;
    ((float4*)out)[(size_t)d * 64 + t] = a;
}

// ---------------- BN2 apply + es/ed fused ------------------------------------
__global__ __launch_bounds__(256) void k_bn2_esed(
    const float* __restrict__ C2, const float* __restrict__ gam,
    const float* __restrict__ bet, float* __restrict__ D)
{
    __shared__ float swa[1024];
    int tid = threadIdx.x;
    for (int t = tid; t < 1024; t += 256) swa[t] = g_wa[t];
    __syncthreads();
    int w = tid >> 5, lane = tid & 31;
    int n = blockIdx.x * 8 + w;
    float4 v = ((const float4*)C2)[(size_t)n * 32 + lane];
    float inv_n = 1.0f / (float)NN;
    float r[4] = {v.x, v.y, v.z, v.w};
#pragma unroll
    for (int j = 0; j < 4; j++) {
        int c = lane * 4 + j;
        float mean = g_bnsum[512 + c] * inv_n;
        float var = g_bnsq[512 + c] * inv_n - mean * mean;
        float y = (r[j] - mean) * rsqrtf(var + BN_EPS) * gam[c] + bet[c];
        r[j] = fmaxf(y, 0.f);
    }
    ((float4*)D)[(size_t)n * 32 + lane] = make_float4(r[0], r[1], r[2], r[3]);

    float p[8];
#pragma unroll
    for (int s = 0; s < 2; s++)
#pragma unroll
        for (int h = 0; h < 4; h++) {
            float4 wv = ((const float4*)swa)[(s * 512 + h * 128) / 4 + lane];
            p[s * 4 + h] = r[0] * wv.x + r[1] * wv.y + r[2] * wv.z + r[3] * wv.w;
        }
#pragma unroll
    for (int o = 16; o > 0; o >>= 1)
#pragma unroll
        for (int j = 0; j < 8; j++)
            p[j] += __shfl_xor_sync(0xffffffffu, p[j], o);
    if (lane < 4) g_es[n * 4 + lane] = p[lane];
    else if (lane < 8) g_ed[n * 4 + (lane - 4)] = p[lane];
}

__device__ __forceinline__ float leaky02(float x) { return x > 0.f ? x : 0.2f * x; }

// ---------------- warp-autonomous GAT aggregation ----------------------------
__global__ __launch_bounds__(256) void k_gat_agg(const float* __restrict__ D,
                                                 float* __restrict__ agg)
{
    int warp = threadIdx.x >> 5;
    int lane = threadIdx.x & 31;
    int d = blockIdx.x * 2 + (warp >> 2);
    int h = warp & 3;
    int st = g_rowptr[d], deg = g_rowptr[d + 1] - st;
    float edv = g_ed[d * 4 + h];
    float eself = leaky02(g_es[d * 4 + h] + edv);

    float m = eself;
    for (int i = lane; i < deg; i += 32)
        m = fmaxf(m, leaky02(g_es[g_csr[st + i] * 4 + h] + edv));
#pragma unroll
    for (int o = 16; o > 0; o >>= 1) m = fmaxf(m, __shfl_xor_sync(0xffffffffu, m, o));
    float z = (lane == 0) ? __expf(eself - m) : 0.f;
    for (int i = lane; i < deg; i += 32)
        z += __expf(leaky02(g_es[g_csr[st + i] * 4 + h] + edv) - m);
#pragma unroll
    for (int o = 16; o > 0; o >>= 1) z += __shfl_xor_sync(0xffffffffu, z, o);
    float invz = 1.f / z;

    const float4* D4 = (const float4*)D;
    float4 acc = make_float4(0.f, 0.f, 0.f, 0.f);
    int i = 0;
    for (; i + 2 <= deg; i += 2) {
        int s0 = g_csr[st + i], s1 = g_csr[st + i + 1];
        float a0 = __expf(leaky02(g_es[s0 * 4 + h] + edv) - m) * invz;
        float a1 = __expf(leaky02(g_es[s1 * 4 + h] + edv) - m) * invz;
        float4 v0 = D4[(size_t)s0 * 32 + lane];
        float4 v1 = D4[(size_t)s1 * 32 + lane];
        acc.x += v0.x * a0 + v1.x * a1;
        acc.y += v0.y * a0 + v1.y * a1;
        acc.z += v0.z * a0 + v1.z * a1;
        acc.w += v0.w * a0 + v1.w * a1;
    }
    if (i < deg) {
        int s0 = g_csr[st + i];
        float a0 = __expf(leaky02(g_es[s0 * 4 + h] + edv) - m) * invz;
        float4 v0 = D4[(size_t)s0 * 32 + lane];
        acc.x += v0.x * a0; acc.y += v0.y * a0; acc.z += v0.z * a0; acc.w += v0.w * a0;
    }
    {
        float a0 = __expf(eself - m) * invz;
        float4 v0 = D4[(size_t)d * 32 + lane];
        acc.x += v0.x * a0; acc.y += v0.y * a0; acc.z += v0.z * a0; acc.w += v0.w * a0;
    }
    ((float4*)agg)[(size_t)d * 128 + h * 32 + lane] = acc;
}

// ---------------- pooling (fused BN4+ReLU), atomic, grid (GG, 8) ------------
__global__ void k_pool_bn(const float* __restrict__ C4buf,
                          const float* __restrict__ gam, const float* __restrict__ bet)
{
    int g = blockIdx.x;
    int chunk = blockIdx.y;      // 0..7
    int c4 = threadIdx.x;        // 128 (float4 over 512 ch)
    int st = g_gstart[g], en = g_gstart[g + 1];
    int cnt = en - st;
    int lo = st + (cnt * chunk) / 8;
    int hi = st + (cnt * (chunk + 1)) / 8;
    float sc[4], sh[4];
    float inv_n = 1.0f / (float)NN;
#pragma unroll
    for (int j = 0; j < 4; j++) {
        int c = c4 * 4 + j;
        float mean = g_bnsum[1536 + c] * inv_n;
        float var = g_bnsq[1536 + c] * inv_n - mean * mean;
        float s = rsqrtf(var + BN_EPS) * gam[c];
        sc[j] = s;
        sh[j] = bet[c] - mean * s;
    }
    const float4* D4 = (const float4*)C4buf;
    float4 s = make_float4(0.f, 0.f, 0.f, 0.f);
    float4 m = make_float4(0.f, 0.f, 0.f, 0.f);   // post-ReLU values >= 0
    for (int i = lo; i < hi; i++) {
        float4 v = D4[(size_t)i * 128 + c4];
        v.x = fmaxf(fmaf(v.x, sc[0], sh[0]), 0.f);
        v.y = fmaxf(fmaf(v.y, sc[1], sh[1]), 0.f);
        v.z = fmaxf(fmaf(v.z, sc[2], sh[2]), 0.f);
        v.w = fmaxf(fmaf(v.w, sc[3], sh[3]), 0.f);
        s.x += v.x; s.y += v.y; s.z += v.z; s.w += v.w;
        m.x = fmaxf(m.x, v.x); m.y = fmaxf(m.y, v.y);
        m.z = fmaxf(m.z, v.z); m.w = fmaxf(m.w, v.w);
    }
    if (lo < hi) {
        float* sp = &g_pooled[g * 1024 + c4 * 4];
        atomicAdd(sp + 0, s.x); atomicAdd(sp + 1, s.y);
        atomicAdd(sp + 2, s.z); atomicAdd(sp + 3, s.w);
        int* mp = (int*)&g_pooled[g * 1024 + 512 + c4 * 4];
        atomicMax(mp + 0, __float_as_int(m.x));
        atomicMax(mp + 1, __float_as_int(m.y));
        atomicMax(mp + 2, __float_as_int(m.z));
        atomicMax(mp + 3, __float_as_int(m.w));
    }
}

// ---------------- FC (divides mean-sum by cnt on load) ----------------------
__global__ __launch_bounds__(128) void k_fc(const float* __restrict__ W,
                                            const float* __restrict__ bias,
                                            float* __restrict__ out)
{
    __shared__ float sp[4][1024];
    int tid = threadIdx.x;
    int j = blockIdx.x * 128 + tid;
    int g0 = blockIdx.y * 4;
    for (int t = tid; t < 4 * 1024; t += 128) {
        int gg = g0 + (t >> 10);
        int c = t & 1023;
        float v = g_pooled[gg * 1024 + c];
        if (c < 512) {
            int cnt = g_gstart[gg + 1] - g_gstart[gg];
            v *= 1.f / (float)max(cnt, 1);
        }
        sp[t >> 10][c] = v;
    }
    __syncthreads();
    float acc[4] = {0.f, 0.f, 0.f, 0.f};
#pragma unroll 4
    for (int kk = 0; kk < 1024; kk++) {
        float wv = W[(size_t)kk * 1024 + j];
#pragma unroll
        for (int g = 0; g < 4; g++) acc[g] += sp[g][kk] * wv;
    }
    float bv = bias[j];
#pragma unroll
    for (int g = 0; g < 4; g++) out[(size_t)(g0 + g) * 1024 + j] = acc[g] + bv;
}

// ---------------- host orchestration ---------------------------------------
extern "C" void kernel_launch(void* const* d_in, const int* in_sizes, int n_in,
                              void* d_out, int out_size)
{
    const float* x        = (const float*)d_in[0];
    const int*   ei       = (const int*)  d_in[1];
    const int*   batch    = (const int*)  d_in[2];
    const float* gcn1_w   = (const float*)d_in[3];
    const float* sage_wl  = (const float*)d_in[5];
    const float* sage_wr  = (const float*)d_in[6];
    const float* gat_w    = (const float*)d_in[8];
    const float* gat_asrc = (const float*)d_in[9];
    const float* gat_adst = (const float*)d_in[10];
    const float* gcn4_w   = (const float*)d_in[12];
    const float* bn1_g = (const float*)d_in[14]; const float* bn1_b = (const float*)d_in[15];
    const float* bn2_g = (const float*)d_in[16]; const float* bn2_b = (const float*)d_in[17];
    const float* bn3_g = (const float*)d_in[18]; const float* bn3_b = (const float*)d_in[19];
    const float* bn4_g = (const float*)d_in[20]; const float* bn4_b = (const float*)d_in[21];
    const float* fc_w  = (const float*)d_in[22]; const float* fc_b  = (const float*)d_in[23];
    float* out = (float*)d_out;

    const int* src = ei;
    const int* dst = ei + EE;

    float *A, *B, *C, *D;
    cudaGetSymbolAddress((void**)&A, g_bufA);
    cudaGetSymbolAddress((void**)&B, g_bufB);
    cudaGetSymbolAddress((void**)&C, g_bufC);
    cudaGetSymbolAddress((void**)&D, g_bufD);

    // setup (zero + wa + gstart) and graph build
    k_setup<<<69, 256>>>(gat_w, gat_asrc, gat_adst, batch);
    k_deg<<<EE / 256, 256>>>(dst);
    k_scan<<<1, 1024>>>();
    k_csr_fill<<<EE / 256, 256>>>(src, dst);

    // ---- layer 1: fused gather + GEMV + BN stats ----
    k_l1<<<NN / 8, 256>>>(x, gcn1_w, C);

    // ---- layer 2: SAGE(64->128) with fused BN1; single GEMM + stats ----
    k_sage_agg_bn<<<NN / 8, 256>>>(C, bn1_g, bn1_b, B);
    k_gemm_f16<<<dim3(1, NN / 128), 256>>>(B, sage_wl, sage_wr, 64, C, NN, 128, 128, 0, 512);
    k_bn2_esed<<<NN / 8, 256>>>(C, bn2_g, bn2_b, D);

    // ---- layer 3: GAT aggregate-then-transform + stats ----
    k_gat_agg<<<NN / 2, 256>>>(D, A);
    k_gemm_f16<<<dim3(2, NN / 128), 256>>>(A, gat_w, nullptr, 0, C, NN, 512, 256, 1, 1024);

    // ---- layer 4: GCN with fused BN3 gather, GEMM + stats ----
    k_gcn_agg4_bn<<<NN / 4, 256>>>(C, bn3_g, bn3_b, B);
    k_gemm_f16<<<dim3(4, NN / 128), 256>>>(B, gcn4_w, gcn4_w, 256, C, NN, 256, 512, 0, 1536);

    // ---- pooling (BN4 fused, parallel atomic) + FC ----
    k_pool_bn<<<dim3(GG, 8), 128>>>(C, bn4_g, bn4_b);
    k_fc<<<dim3(8, 8), 128>>>(fc_w, fc_b, out);
}

// round 14
// speedup vs baseline: 1.2095x; 1.0257x over previous
#include <cuda_runtime.h>
#include <cuda_fp16.h>
#include <mma.h>
#include <math.h>

using namespace nvcuda;

#define NN 16384
#define EE 131072
#define GG 32
#define BN_EPS 1e-5f

// ---------------- scratch (device globals: no allocation allowed) ----------
__device__ float g_bufA[NN * 512];    // GAT per-head agg [N,512] (32 MB)
__device__ float g_bufB[NN * 512];    // packed sage / agg        (32 MB)
__device__ float g_bufC[NN * 512];    // pre-BN buffers           (32 MB)
__device__ float g_bufD[NN * 512];    // post-BN layer2 output    (32 MB)
__device__ float g_es[NN * 4];
__device__ float g_ed[NN * 4];
__device__ int   g_deg[NN];
__device__ int   g_rowptr[NN + 1];
__device__ int   g_cursor[NN];
__device__ int   g_csr[EE];
__device__ float g_dis[NN];
__device__ float g_bnsum[2048];       // layers at offsets 0,512,1024,1536
__device__ float g_bnsq[2048];
__device__ float g_wa[1024];          // [sel(2)][head(4)][k(128)]
__device__ float g_pooled[GG * 1024]; // [g][0:512]=sum, [512:1024]=max (atomics)
__device__ int   g_gstart[GG + 1];

// ---------------- fused setup: zero + wa projection + gstart ----------------
__global__ void k_setup(const float* __restrict__ gat_w,
                        const float* __restrict__ asrc, const float* __restrict__ adst,
                        const int* __restrict__ batch)
{
    int b = blockIdx.x;
    int tid = threadIdx.x;
    if (b < 64) {
        int i = b * 256 + tid;
        g_deg[i] = 0;
        g_cursor[i] = 0;
        if (i < 2048) { g_bnsum[i] = 0.f; g_bnsq[i] = 0.f; }
        g_pooled[i] = 0.f;
        g_pooled[i + 16384] = 0.f;
    } else if (b < 68) {
        int sub = (b - 64) * 2 + (tid >> 7);   // 0..7
        int k = tid & 127;
        int sel = sub >> 2, h = sub & 3;
        const float* a = (sel == 0) ? asrc : adst;
        float s = 0.f;
        for (int c = 0; c < 256; c++)
            s += gat_w[(size_t)k * 1024 + h * 256 + c] * a[h * 256 + c];
        g_wa[sel * 512 + h * 128 + k] = s;
    } else {
        int g = tid;
        if (g <= GG) {
            int lo = 0, hi = NN;
            while (lo < hi) {
                int mid = (lo + hi) >> 1;
                if (batch[mid] < g) lo = mid + 1;
                else hi = mid;
            }
            g_gstart[g] = lo;
        }
    }
}

__global__ void k_deg(const int* __restrict__ dst) {
    int e = blockIdx.x * blockDim.x + threadIdx.x;
    if (e < EE) atomicAdd(&g_deg[dst[e]], 1);
}

__global__ void k_scan() {
    __shared__ int sh[1024];
    int tid = threadIdx.x;
    int base = tid * 16;
    int s = 0;
    for (int i = 0; i < 16; i++) s += g_deg[base + i];
    sh[tid] = s;
    __syncthreads();
    for (int off = 1; off < 1024; off <<= 1) {
        int v = (tid >= off) ? sh[tid - off] : 0;
        __syncthreads();
        sh[tid] += v;
        __syncthreads();
    }
    int run = sh[tid] - s;
    for (int i = 0; i < 16; i++) {
        int dg = g_deg[base + i];
        g_rowptr[base + i] = run;
        g_dis[base + i] = rsqrtf((float)dg + 1.0f);
        run += dg;
    }
    if (tid == 1023) g_rowptr[NN] = sh[1023];
}

__global__ void k_csr_fill(const int* __restrict__ src, const int* __restrict__ dst) {
    int e = blockIdx.x * blockDim.x + threadIdx.x;
    if (e < EE) {
        int d = dst[e];
        int pos = g_rowptr[d] + atomicAdd(&g_cursor[d], 1);
        g_csr[pos] = src[e];
    }
}

// ---------------- layer 1 fully fused: gather(5ch) + 5x64 GEMV + BN stats ---
__global__ __launch_bounds__(256) void k_l1(const float* __restrict__ x,
                                            const float* __restrict__ W,
                                            float* __restrict__ C)
{
    __shared__ float sW[320];
    __shared__ float ssum[64], ssq[64];
    int tid = threadIdx.x;
    for (int t = tid; t < 320; t += 256) sW[t] = W[t];
    if (tid < 64) { ssum[tid] = 0.f; ssq[tid] = 0.f; }
    __syncthreads();

    int w = tid >> 5, lane = tid & 31;
    int d = blockIdx.x * 8 + w;
    int st = g_rowptr[d], deg = g_rowptr[d + 1] - st;
    float disd = g_dis[d];
    float a = 0.f;
    for (int i = 0; i < deg; i++) {
        int s = g_csr[st + i];
        float wt = g_dis[s];
        if (lane < 5) a += x[s * 5 + lane] * wt;
    }
    if (lane < 5) a = (a + x[d * 5 + lane] * disd) * disd;
    float xa0 = __shfl_sync(0xffffffffu, a, 0);
    float xa1 = __shfl_sync(0xffffffffu, a, 1);
    float xa2 = __shfl_sync(0xffffffffu, a, 2);
    float xa3 = __shfl_sync(0xffffffffu, a, 3);
    float xa4 = __shfl_sync(0xffffffffu, a, 4);

    int c0 = lane, c1 = lane + 32;
    float h0 = xa0 * sW[c0] + xa1 * sW[64 + c0] + xa2 * sW[128 + c0]
             + xa3 * sW[192 + c0] + xa4 * sW[256 + c0];
    float h1 = xa0 * sW[c1] + xa1 * sW[64 + c1] + xa2 * sW[128 + c1]
             + xa3 * sW[192 + c1] + xa4 * sW[256 + c1];
    C[(size_t)d * 64 + c0] = h0;
    C[(size_t)d * 64 + c1] = h1;
    atomicAdd(&ssum[c0], h0); atomicAdd(&ssq[c0], h0 * h0);
    atomicAdd(&ssum[c1], h1); atomicAdd(&ssq[c1], h1 * h1);
    __syncthreads();
    if (tid < 64) {
        atomicAdd(&g_bnsum[tid], ssum[tid]);
        atomicAdd(&g_bnsq[tid], ssq[tid]);
    }
}

// ---------------- SAGE aggregation with fused BN1+ReLU ----------------------
__global__ __launch_bounds__(256) void k_sage_agg_bn(
    const float* __restrict__ C1,
    const float* __restrict__ gam, const float* __restrict__ bet,
    float* __restrict__ P)
{
    int w = threadIdx.x >> 5;
    int d = blockIdx.x * 8 + w;
    int lane = threadIdx.x & 31;
    int st = g_rowptr[d], deg = g_rowptr[d + 1] - st;
    int half = lane >> 4;
    int q = lane & 15;             // float4 chunk of 64 ch
    float sc[4], sh[4];
    float inv_n = 1.0f / (float)NN;
#pragma unroll
    for (int j = 0; j < 4; j++) {
        int c = q * 4 + j;
        float mean = g_bnsum[c] * inv_n;
        float var = g_bnsq[c] * inv_n - mean * mean;
        float s = rsqrtf(var + BN_EPS) * gam[c];
        sc[j] = s;
        sh[j] = bet[c] - mean * s;
    }
    const float4* C4 = (const float4*)C1;   // row stride 16
    float4 a = make_float4(0.f, 0.f, 0.f, 0.f);
    for (int i = 0; i < deg; i += 2) {
        int idx = i + half;
        if (idx < deg) {
            int s = g_csr[st + idx];
            float4 v = C4[(size_t)s * 16 + q];
            a.x += fmaxf(fmaf(v.x, sc[0], sh[0]), 0.f);
            a.y += fmaxf(fmaf(v.y, sc[1], sh[1]), 0.f);
            a.z += fmaxf(fmaf(v.z, sc[2], sh[2]), 0.f);
            a.w += fmaxf(fmaf(v.w, sc[3], sh[3]), 0.f);
        }
    }
    a.x += __shfl_xor_sync(0xffffffffu, a.x, 16);
    a.y += __shfl_xor_sync(0xffffffffu, a.y, 16);
    a.z += __shfl_xor_sync(0xffffffffu, a.z, 16);
    a.w += __shfl_xor_sync(0xffffffffu, a.w, 16);
    float4 vd = C4[(size_t)d * 16 + q];
    float4 hd;
    hd.x = fmaxf(fmaf(vd.x, sc[0], sh[0]), 0.f);
    hd.y = fmaxf(fmaf(vd.y, sc[1], sh[1]), 0.f);
    hd.z = fmaxf(fmaf(vd.z, sc[2], sh[2]), 0.f);
    hd.w = fmaxf(fmaf(vd.w, sc[3], sh[3]), 0.f);
    if (lane < 16) {
        float inv = 1.f / (float)max(deg, 1);
        float4* P4 = (float4*)P;
        P4[(size_t)d * 32 + q] = make_float4(a.x * inv, a.y * inv, a.z * inv, a.w * inv);
        P4[(size_t)d * 32 + 16 + q] = hd;
    }
}

// ---------------- FP16 tensor-core GEMM (BK=16) + fused BN-stat epilogue ----
__device__ __forceinline__ void st_half4(__half* p, float4 v) {
    ((__half2*)p)[0] = __floats2half2_rn(v.x, v.y);
    ((__half2*)p)[1] = __floats2half2_rn(v.z, v.w);
}

__global__ __launch_bounds__(256, 2) void k_gemm_f16(
    const float* __restrict__ A,
    const float* __restrict__ W1, const float* __restrict__ W2, int ksplit,
    float* __restrict__ C, int M, int K, int Nn, int gatmode, int statoff)
{
    __shared__ __half As[128][24];
    __shared__ __half Bs[16][136];
    __shared__ float red[2][128][2];

    int tid = threadIdx.x;
    int warp = tid >> 5;
    int wm = warp >> 2;
    int wn = warp & 3;
    int row0 = blockIdx.y * 128, col0 = blockIdx.x * 128;

    int a_r[2], a_c[2];
#pragma unroll
    for (int i = 0; i < 2; i++) {
        int s = tid * 2 + i;
        a_r[i] = s >> 2;
        a_c[i] = (s & 3) * 4;
    }
    int b_r[2], b_c[2];
#pragma unroll
    for (int i = 0; i < 2; i++) {
        int s = tid + 256 * i;
        b_r[i] = s >> 5;
        b_c[i] = (s & 31) * 4;
    }

    const float* Abase = A + (size_t)row0 * K;

    float4 cA[2], cB[2];
#pragma unroll
    for (int i = 0; i < 2; i++) {
        cA[i] = *(const float4*)(Abase + (size_t)a_r[i] * K + a_c[i]);
        int k = b_r[i];
        const float* wp;
        if (gatmode) wp = W1 + (size_t)(k & 127) * 1024 + (k >> 7) * 256;
        else wp = (k < ksplit) ? (W1 + (size_t)k * Nn)
                               : (W2 + (size_t)(k - ksplit) * Nn);
        cB[i] = *(const float4*)(wp + col0 + b_c[i]);
    }

    wmma::fragment<wmma::accumulator, 16, 16, 16, float> acc[4][2];
#pragma unroll
    for (int i = 0; i < 4; i++)
#pragma unroll
        for (int j = 0; j < 2; j++) wmma::fill_fragment(acc[i][j], 0.f);

    for (int k0 = 0; k0 < K; k0 += 16) {
#pragma unroll
        for (int i = 0; i < 2; i++) {
            st_half4(&As[a_r[i]][a_c[i]], cA[i]);
            st_half4(&Bs[b_r[i]][b_c[i]], cB[i]);
        }
        __syncthreads();
        if (k0 + 16 < K) {
#pragma unroll
            for (int i = 0; i < 2; i++) {
                cA[i] = *(const float4*)(Abase + (size_t)a_r[i] * K + (k0 + 16) + a_c[i]);
                int k = k0 + 16 + b_r[i];
                const float* wp;
                if (gatmode) wp = W1 + (size_t)(k & 127) * 1024 + (k >> 7) * 256;
                else wp = (k < ksplit) ? (W1 + (size_t)k * Nn)
                                       : (W2 + (size_t)(k - ksplit) * Nn);
                cB[i] = *(const float4*)(wp + col0 + b_c[i]);
            }
        }
        {
            wmma::fragment<wmma::matrix_a, 16, 16, 16, __half, wmma::row_major> af[4];
            wmma::fragment<wmma::matrix_b, 16, 16, 16, __half, wmma::row_major> bf[2];
#pragma unroll
            for (int i = 0; i < 4; i++)
                wmma::load_matrix_sync(af[i], &As[wm * 64 + i * 16][0], 24);
#pragma unroll
            for (int j = 0; j < 2; j++)
                wmma::load_matrix_sync(bf[j], &Bs[0][wn * 32 + j * 16], 136);
#pragma unroll
            for (int i = 0; i < 4; i++)
#pragma unroll
                for (int j = 0; j < 2; j++)
                    wmma::mma_sync(acc[i][j], af[i], bf[j], acc[i][j]);
        }
        __syncthreads();
    }

#pragma unroll
    for (int i = 0; i < 4; i++)
#pragma unroll
        for (int j = 0; j < 2; j++) {
            int gr = row0 + wm * 64 + i * 16;
            int gc = col0 + wn * 32 + j * 16;
            wmma::store_matrix_sync(C + (size_t)gr * Nn + gc, acc[i][j], Nn,
                                    wmma::mem_row_major);
        }

    if (statoff >= 0) {
        __syncthreads();
        int c = tid & 127, rh = tid >> 7;
        const float* cp = C + (size_t)(row0 + rh * 64) * Nn + col0 + c;
        float s = 0.f, q = 0.f;
#pragma unroll 4
        for (int r = 0; r < 64; r++) {
            float v = cp[(size_t)r * Nn];
            s += v;
            q += v * v;
        }
        red[rh][c][0] = s;
        red[rh][c][1] = q;
        __syncthreads();
        if (rh == 0) {
            s += red[1][c][0];
            q += red[1][c][1];
            atomicAdd(&g_bnsum[statoff + col0 + c], s);
            atomicAdd(&g_bnsq[statoff + col0 + c], q);
        }
    }
}

// ---------------- layer-4 GCN gather with fused BN3+ReLU (MLP 4) -----------
__global__ __launch_bounds__(256) void k_gcn_agg4_bn(
    const float* __restrict__ C3,
    const float* __restrict__ gam, const float* __restrict__ bet,
    float* __restrict__ out)
{
    int tid = threadIdx.x;
    int d = blockIdx.x * 4 + (tid >> 6);
    int t = tid & 63;
    int st = g_rowptr[d], deg = g_rowptr[d + 1] - st;
    float disd = g_dis[d];
    float sc[4], sh[4];
    float inv_n = 1.0f / (float)NN;
#pragma unroll
    for (int j = 0; j < 4; j++) {
        int c = t * 4 + j;
        float mean = g_bnsum[1024 + c] * inv_n;
        float var = g_bnsq[1024 + c] * inv_n - mean * mean;
        float s = rsqrtf(var + BN_EPS) * gam[c];
        sc[j] = s;
        sh[j] = bet[c] - mean * s;
    }
    const float4* in4 = (const float4*)C3;
    float4 a = make_float4(0.f, 0.f, 0.f, 0.f);
    int i = 0;
    for (; i + 4 <= deg; i += 4) {
        int s0 = g_csr[st + i], s1 = g_csr[st + i + 1];
        int s2 = g_csr[st + i + 2], s3 = g_csr[st + i + 3];
        float w0 = g_dis[s0], w1 = g_dis[s1], w2 = g_dis[s2], w3 = g_dis[s3];
        float4 v0 = in4[(size_t)s0 * 64 + t];
        float4 v1 = in4[(size_t)s1 * 64 + t];
        float4 v2 = in4[(size_t)s2 * 64 + t];
        float4 v3 = in4[(size_t)s3 * 64 + t];
        a.x += fmaxf(fmaf(v0.x, sc[0], sh[0]), 0.f) * w0 + fmaxf(fmaf(v1.x, sc[0], sh[0]), 0.f) * w1
             + fmaxf(fmaf(v2.x, sc[0], sh[0]), 0.f) * w2 + fmaxf(fmaf(v3.x, sc[0], sh[0]), 0.f) * w3;
        a.y += fmaxf(fmaf(v0.y, sc[1], sh[1]), 0.f) * w0 + fmaxf(fmaf(v1.y, sc[1], sh[1]), 0.f) * w1
             + fmaxf(fmaf(v2.y, sc[1], sh[1]), 0.f) * w2 + fmaxf(fmaf(v3.y, sc[1], sh[1]), 0.f) * w3;
        a.z += fmaxf(fmaf(v0.z, sc[2], sh[2]), 0.f) * w0 + fmaxf(fmaf(v1.z, sc[2], sh[2]), 0.f) * w1
             + fmaxf(fmaf(v2.z, sc[2], sh[2]), 0.f) * w2 + fmaxf(fmaf(v3.z, sc[2], sh[2]), 0.f) * w3;
        a.w += fmaxf(fmaf(v0.w, sc[3], sh[3]), 0.f) * w0 + fmaxf(fmaf(v1.w, sc[3], sh[3]), 0.f) * w1
             + fmaxf(fmaf(v2.w, sc[3], sh[3]), 0.f) * w2 + fmaxf(fmaf(v3.w, sc[3], sh[3]), 0.f) * w3;
    }
    for (; i < deg; i++) {
        int s0 = g_csr[st + i];
        float w0 = g_dis[s0];
        float4 v0 = in4[(size_t)s0 * 64 + t];
        a.x += fmaxf(fmaf(v0.x, sc[0], sh[0]), 0.f) * w0;
        a.y += fmaxf(fmaf(v0.y, sc[1], sh[1]), 0.f) * w0;
        a.z += fmaxf(fmaf(v0.z, sc[2], sh[2]), 0.f) * w0;
        a.w += fmaxf(fmaf(v0.w, sc[3], sh[3]), 0.f) * w0;
    }
    float4 v = in4[(size_t)d * 64 + t];
    a.x += fmaxf(fmaf(v.x, sc[0], sh[0]), 0.f) * disd;
    a.y += fmaxf(fmaf(v.y, sc[1], sh[1]), 0.f) * disd;
    a.z += fmaxf(fmaf(v.z, sc[2], sh[2]), 0.f) * disd;
    a.w += fmaxf(fmaf(v.w, sc[3], sh[3]), 0.f) * disd;
    a.x *= disd; a.y *= disd; a.z *= disd; a.w *= disd;
    ((float4*)out)[(size_t)d * 64 + t] = a;
}

// ---------------- BN2 apply + es/ed fused ------------------------------------
__global__ __launch_bounds__(256) void k_bn2_esed(
    const float* __restrict__ C2, const float* __restrict__ gam,
    const float* __restrict__ bet, float* __restrict__ D)
{
    __shared__ float swa[1024];
    int tid = threadIdx.x;
    for (int t = tid; t < 1024; t += 256) swa[t] = g_wa[t];
    __syncthreads();
    int w = tid >> 5, lane = tid & 31;
    int n = blockIdx.x * 8 + w;
    float4 v = ((const float4*)C2)[(size_t)n * 32 + lane];
    float inv_n = 1.0f / (float)NN;
    float r[4] = {v.x, v.y, v.z, v.w};
#pragma unroll
    for (int j = 0; j < 4; j++) {
        int c = lane * 4 + j;
        float mean = g_bnsum[512 + c] * inv_n;
        float var = g_bnsq[512 + c] * inv_n - mean * mean;
        float y = (r[j] - mean) * rsqrtf(var + BN_EPS) * gam[c] + bet[c];
        r[j] = fmaxf(y, 0.f);
    }
    ((float4*)D)[(size_t)n * 32 + lane] = make_float4(r[0], r[1], r[2], r[3]);

    float p[8];
#pragma unroll
    for (int s = 0; s < 2; s++)
#pragma unroll
        for (int h = 0; h < 4; h++) {
            float4 wv = ((const float4*)swa)[(s * 512 + h * 128) / 4 + lane];
            p[s * 4 + h] = r[0] * wv.x + r[1] * wv.y + r[2] * wv.z + r[3] * wv.w;
        }
#pragma unroll
    for (int o = 16; o > 0; o >>= 1)
#pragma unroll
        for (int j = 0; j < 8; j++)
            p[j] += __shfl_xor_sync(0xffffffffu, p[j], o);
    if (lane < 4) g_es[n * 4 + lane] = p[lane];
    else if (lane < 8) g_ed[n * 4 + (lane - 4)] = p[lane];
}

__device__ __forceinline__ float leaky02(float x) { return x > 0.f ? x : 0.2f * x; }

// ---------------- warp-autonomous GAT aggregation with alpha cache ----------
// warp = (node, head); per-warp smem caches edge src + exp values so the
// channel loop reads broadcast alphas instead of 32x-redundant exp/loads.
__global__ __launch_bounds__(256) void k_gat_agg(const float* __restrict__ D,
                                                 float* __restrict__ agg)
{
    __shared__ float se[8][66];
    __shared__ int   ss[8][66];
    int warp = threadIdx.x >> 5;
    int lane = threadIdx.x & 31;
    int d = blockIdx.x * 2 + (warp >> 2);
    int h = warp & 3;
    int st = g_rowptr[d], deg = g_rowptr[d + 1] - st;
    float edv = g_ed[d * 4 + h];
    float eself = leaky02(g_es[d * 4 + h] + edv);
    int tot = deg + 1;   // self loop at index deg
    const float4* D4 = (const float4*)D;
    float4 acc = make_float4(0.f, 0.f, 0.f, 0.f);

    if (tot <= 64) {
        // phase 1: compute e_i once, cache
        for (int i = lane; i < tot; i += 32) {
            int s = (i < deg) ? g_csr[st + i] : d;
            ss[warp][i] = s;
            se[warp][i] = (i < deg) ? leaky02(g_es[s * 4 + h] + edv) : eself;
        }
        __syncwarp();
        // phase 2: max
        float m = -3.4e38f;
        for (int i = lane; i < tot; i += 32) m = fmaxf(m, se[warp][i]);
#pragma unroll
        for (int o = 16; o > 0; o >>= 1) m = fmaxf(m, __shfl_xor_sync(0xffffffffu, m, o));
        // phase 3: exp + sum, overwrite cache with exp
        float z = 0.f;
        for (int i = lane; i < tot; i += 32) {
            float ex = __expf(se[warp][i] - m);
            se[warp][i] = ex;
            z += ex;
        }
        __syncwarp();
#pragma unroll
        for (int o = 16; o > 0; o >>= 1) z += __shfl_xor_sync(0xffffffffu, z, o);
        float invz = 1.f / z;
        // phase 4: channel aggregation with broadcast alphas
        int i = 0;
        for (; i + 2 <= tot; i += 2) {
            int s0 = ss[warp][i], s1 = ss[warp][i + 1];
            float a0 = se[warp][i] * invz, a1 = se[warp][i + 1] * invz;
            float4 v0 = D4[(size_t)s0 * 32 + lane];
            float4 v1 = D4[(size_t)s1 * 32 + lane];
            acc.x += v0.x * a0 + v1.x * a1;
            acc.y += v0.y * a0 + v1.y * a1;
            acc.z += v0.z * a0 + v1.z * a1;
            acc.w += v0.w * a0 + v1.w * a1;
        }
        if (i < tot) {
            int s0 = ss[warp][i];
            float a0 = se[warp][i] * invz;
            float4 v0 = D4[(size_t)s0 * 32 + lane];
            acc.x += v0.x * a0; acc.y += v0.y * a0; acc.z += v0.z * a0; acc.w += v0.w * a0;
        }
    } else {
        // fallback: recompute path (deg > 63, statistically absent)
        float m = eself;
        for (int i = lane; i < deg; i += 32)
            m = fmaxf(m, leaky02(g_es[g_csr[st + i] * 4 + h] + edv));
#pragma unroll
        for (int o = 16; o > 0; o >>= 1) m = fmaxf(m, __shfl_xor_sync(0xffffffffu, m, o));
        float z = (lane == 0) ? __expf(eself - m) : 0.f;
        for (int i = lane; i < deg; i += 32)
            z += __expf(leaky02(g_es[g_csr[st + i] * 4 + h] + edv) - m);
#pragma unroll
        for (int o = 16; o > 0; o >>= 1) z += __shfl_xor_sync(0xffffffffu, z, o);
        float invz = 1.f / z;
        for (int i = 0; i < deg; i++) {
            int s0 = g_csr[st + i];
            float a0 = __expf(leaky02(g_es[s0 * 4 + h] + edv) - m) * invz;
            float4 v0 = D4[(size_t)s0 * 32 + lane];
            acc.x += v0.x * a0; acc.y += v0.y * a0; acc.z += v0.z * a0; acc.w += v0.w * a0;
        }
        float a0 = __expf(eself - m) * invz;
        float4 v0 = D4[(size_t)d * 32 + lane];
        acc.x += v0.x * a0; acc.y += v0.y * a0; acc.z += v0.z * a0; acc.w += v0.w * a0;
    }
    ((float4*)agg)[(size_t)d * 128 + h * 32 + lane] = acc;
}

// ---------------- pooling (fused BN4+ReLU), atomic, grid (GG, 8) ------------
__global__ void k_pool_bn(const float* __restrict__ C4buf,
                          const float* __restrict__ gam, const float* __restrict__ bet)
{
    int g = blockIdx.x;
    int chunk = blockIdx.y;      // 0..7
    int c4 = threadIdx.x;        // 128 (float4 over 512 ch)
    int st = g_gstart[g], en = g_gstart[g + 1];
    int cnt = en - st;
    int lo = st + (cnt * chunk) / 8;
    int hi = st + (cnt * (chunk + 1)) / 8;
    float sc[4], sh[4];
    float inv_n = 1.0f / (float)NN;
#pragma unroll
    for (int j = 0; j < 4; j++) {
        int c = c4 * 4 + j;
        float mean = g_bnsum[1536 + c] * inv_n;
        float var = g_bnsq[1536 + c] * inv_n - mean * mean;
        float s = rsqrtf(var + BN_EPS) * gam[c];
        sc[j] = s;
        sh[j] = bet[c] - mean * s;
    }
    const float4* D4 = (const float4*)C4buf;
    float4 s = make_float4(0.f, 0.f, 0.f, 0.f);
    float4 m = make_float4(0.f, 0.f, 0.f, 0.f);   // post-ReLU values >= 0
    for (int i = lo; i < hi; i++) {
        float4 v = D4[(size_t)i * 128 + c4];
        v.x = fmaxf(fmaf(v.x, sc[0], sh[0]), 0.f);
        v.y = fmaxf(fmaf(v.y, sc[1], sh[1]), 0.f);
        v.z = fmaxf(fmaf(v.z, sc[2], sh[2]), 0.f);
        v.w = fmaxf(fmaf(v.w, sc[3], sh[3]), 0.f);
        s.x += v.x; s.y += v.y; s.z += v.z; s.w += v.w;
        m.x = fmaxf(m.x, v.x); m.y = fmaxf(m.y, v.y);
        m.z = fmaxf(m.z, v.z); m.w = fmaxf(m.w, v.w);
    }
    if (lo < hi) {
        float* sp = &g_pooled[g * 1024 + c4 * 4];
        atomicAdd(sp + 0, s.x); atomicAdd(sp + 1, s.y);
        atomicAdd(sp + 2, s.z); atomicAdd(sp + 3, s.w);
        int* mp = (int*)&g_pooled[g * 1024 + 512 + c4 * 4];
        atomicMax(mp + 0, __float_as_int(m.x));
        atomicMax(mp + 1, __float_as_int(m.y));
        atomicMax(mp + 2, __float_as_int(m.z));
        atomicMax(mp + 3, __float_as_int(m.w));
    }
}

// ---------------- FC (divides mean-sum by cnt on load) ----------------------
__global__ __launch_bounds__(128) void k_fc(const float* __restrict__ W,
                                            const float* __restrict__ bias,
                                            float* __restrict__ out)
{
    __shared__ float sp[4][1024];
    int tid = threadIdx.x;
    int j = blockIdx.x * 128 + tid;
    int g0 = blockIdx.y * 4;
    for (int t = tid; t < 4 * 1024; t += 128) {
        int gg = g0 + (t >> 10);
        int c = t & 1023;
        float v = g_pooled[gg * 1024 + c];
        if (c < 512) {
            int cnt = g_gstart[gg + 1] - g_gstart[gg];
            v *= 1.f / (float)max(cnt, 1);
        }
        sp[t >> 10][c] = v;
    }
    __syncthreads();
    float acc[4] = {0.f, 0.f, 0.f, 0.f};
#pragma unroll 4
    for (int kk = 0; kk < 1024; kk++) {
        float wv = W[(size_t)kk * 1024 + j];
#pragma unroll
        for (int g = 0; g < 4; g++) acc[g] += sp[g][kk] * wv;
    }
    float bv = bias[j];
#pragma unroll
    for (int g = 0; g < 4; g++) out[(size_t)(g0 + g) * 1024 + j] = acc[g] + bv;
}

// ---------------- host orchestration ---------------------------------------
extern "C" void kernel_launch(void* const* d_in, const int* in_sizes, int n_in,
                              void* d_out, int out_size)
{
    const float* x        = (const float*)d_in[0];
    const int*   ei       = (const int*)  d_in[1];
    const int*   batch    = (const int*)  d_in[2];
    const float* gcn1_w   = (const float*)d_in[3];
    const float* sage_wl  = (const float*)d_in[5];
    const float* sage_wr  = (const float*)d_in[6];
    const float* gat_w    = (const float*)d_in[8];
    const float* gat_asrc = (const float*)d_in[9];
    const float* gat_adst = (const float*)d_in[10];
    const float* gcn4_w   = (const float*)d_in[12];
    const float* bn1_g = (const float*)d_in[14]; const float* bn1_b = (const float*)d_in[15];
    const float* bn2_g = (const float*)d_in[16]; const float* bn2_b = (const float*)d_in[17];
    const float* bn3_g = (const float*)d_in[18]; const float* bn3_b = (const float*)d_in[19];
    const float* bn4_g = (const float*)d_in[20]; const float* bn4_b = (const float*)d_in[21];
    const float* fc_w  = (const float*)d_in[22]; const float* fc_b  = (const float*)d_in[23];
    float* out = (float*)d_out;

    const int* src = ei;
    const int* dst = ei + EE;

    float *A, *B, *C, *D;
    cudaGetSymbolAddress((void**)&A, g_bufA);
    cudaGetSymbolAddress((void**)&B, g_bufB);
    cudaGetSymbolAddress((void**)&C, g_bufC);
    cudaGetSymbolAddress((void**)&D, g_bufD);

    // setup (zero + wa + gstart) and graph build
    k_setup<<<69, 256>>>(gat_w, gat_asrc, gat_adst, batch);
    k_deg<<<EE / 256, 256>>>(dst);
    k_scan<<<1, 1024>>>();
    k_csr_fill<<<EE / 256, 256>>>(src, dst);

    // ---- layer 1: fused gather + GEMV + BN stats ----
    k_l1<<<NN / 8, 256>>>(x, gcn1_w, C);

    // ---- layer 2: SAGE(64->128) with fused BN1; single GEMM + stats ----
    k_sage_agg_bn<<<NN / 8, 256>>>(C, bn1_g, bn1_b, B);
    k_gemm_f16<<<dim3(1, NN / 128), 256>>>(B, sage_wl, sage_wr, 64, C, NN, 128, 128, 0, 512);
    k_bn2_esed<<<NN / 8, 256>>>(C, bn2_g, bn2_b, D);

    // ---- layer 3: GAT aggregate-then-transform + stats ----
    k_gat_agg<<<NN / 2, 256>>>(D, A);
    k_gemm_f16<<<dim3(2, NN / 128), 256>>>(A, gat_w, nullptr, 0, C, NN, 512, 256, 1, 1024);

    // ---- layer 4: GCN with fused BN3 gather, GEMM + stats ----
    k_gcn_agg4_bn<<<NN / 4, 256>>>(C, bn3_g, bn3_b, B);
    k_gemm_f16<<<dim3(4, NN / 128), 256>>>(B, gcn4_w, gcn4_w, 256, C, NN, 256, 512, 0, 1536);

    // ---- pooling (BN4 fused, parallel atomic) + FC ----
    k_pool_bn<<<dim3(GG, 8), 128>>>(C, bn4_g, bn4_b);
    k_fc<<<dim3(8, 8), 128>>>(fc_w, fc_b, out);
}

// round 15
// speedup vs baseline: 1.2417x; 1.0266x over previous
#include <cuda_runtime.h>
#include <cuda_fp16.h>
#include <mma.h>
#include <math.h>

using namespace nvcuda;

#define NN 16384
#define EE 131072
#define GG 32
#define BN_EPS 1e-5f

// ---------------- scratch (device globals: no allocation allowed) ----------
__device__ float g_bufA[NN * 512];    // GAT per-head agg [N,512] (32 MB)
__device__ float g_bufB[NN * 512];    // packed sage / agg        (32 MB)
__device__ float g_bufC[NN * 512];    // pre-BN buffers           (32 MB)
__device__ float g_bufD[NN * 512];    // post-BN layer2 output    (32 MB)
__device__ float g_es[NN * 4];
__device__ float g_ed[NN * 4];
__device__ int   g_deg[NN];
__device__ int   g_rowptr[NN + 1];
__device__ int   g_cursor[NN];
__device__ int   g_csr[EE];
__device__ float g_dis[NN];
__device__ float g_bnsum[2048];       // layers at offsets 0,512,1024,1536
__device__ float g_bnsq[2048];
__device__ float g_wa[1024];          // [sel(2)][head(4)][k(128)]
__device__ float g_pooled[GG * 1024]; // [g][0:512]=sum, [512:1024]=max (atomics)
__device__ int   g_gstart[GG + 1];

// ---------------- fused setup: zero + wa projection + gstart ----------------
__global__ void k_setup(const float* __restrict__ gat_w,
                        const float* __restrict__ asrc, const float* __restrict__ adst,
                        const int* __restrict__ batch)
{
    int b = blockIdx.x;
    int tid = threadIdx.x;
    if (b < 64) {
        int i = b * 256 + tid;
        g_deg[i] = 0;
        g_cursor[i] = 0;
        if (i < 2048) { g_bnsum[i] = 0.f; g_bnsq[i] = 0.f; }
        g_pooled[i] = 0.f;
        g_pooled[i + 16384] = 0.f;
    } else if (b < 68) {
        int sub = (b - 64) * 2 + (tid >> 7);   // 0..7
        int k = tid & 127;
        int sel = sub >> 2, h = sub & 3;
        const float* a = (sel == 0) ? asrc : adst;
        float s = 0.f;
        for (int c = 0; c < 256; c++)
            s += gat_w[(size_t)k * 1024 + h * 256 + c] * a[h * 256 + c];
        g_wa[sel * 512 + h * 128 + k] = s;
    } else {
        int g = tid;
        if (g <= GG) {
            int lo = 0, hi = NN;
            while (lo < hi) {
                int mid = (lo + hi) >> 1;
                if (batch[mid] < g) lo = mid + 1;
                else hi = mid;
            }
            g_gstart[g] = lo;
        }
    }
}

__global__ void k_deg(const int* __restrict__ dst) {
    int e = blockIdx.x * blockDim.x + threadIdx.x;
    if (e < EE) atomicAdd(&g_deg[dst[e]], 1);
}

__global__ void k_scan() {
    __shared__ int sh[1024];
    int tid = threadIdx.x;
    int base = tid * 16;
    int s = 0;
    for (int i = 0; i < 16; i++) s += g_deg[base + i];
    sh[tid] = s;
    __syncthreads();
    for (int off = 1; off < 1024; off <<= 1) {
        int v = (tid >= off) ? sh[tid - off] : 0;
        __syncthreads();
        sh[tid] += v;
        __syncthreads();
    }
    int run = sh[tid] - s;
    for (int i = 0; i < 16; i++) {
        int dg = g_deg[base + i];
        g_rowptr[base + i] = run;
        g_dis[base + i] = rsqrtf((float)dg + 1.0f);
        run += dg;
    }
    if (tid == 1023) g_rowptr[NN] = sh[1023];
}

__global__ void k_csr_fill(const int* __restrict__ src, const int* __restrict__ dst) {
    int e = blockIdx.x * blockDim.x + threadIdx.x;
    if (e < EE) {
        int d = dst[e];
        int pos = g_rowptr[d] + atomicAdd(&g_cursor[d], 1);
        g_csr[pos] = src[e];
    }
}

// ---------------- layer 1 fully fused: gather(5ch) + 5x64 GEMV + BN stats ---
__global__ __launch_bounds__(256) void k_l1(const float* __restrict__ x,
                                            const float* __restrict__ W,
                                            float* __restrict__ C)
{
    __shared__ float sW[320];
    __shared__ float ssum[64], ssq[64];
    int tid = threadIdx.x;
    for (int t = tid; t < 320; t += 256) sW[t] = W[t];
    if (tid < 64) { ssum[tid] = 0.f; ssq[tid] = 0.f; }
    __syncthreads();

    int w = tid >> 5, lane = tid & 31;
    int d = blockIdx.x * 8 + w;
    int st = g_rowptr[d], deg = g_rowptr[d + 1] - st;
    float disd = g_dis[d];
    float a = 0.f;
    for (int i = 0; i < deg; i++) {
        int s = g_csr[st + i];
        float wt = g_dis[s];
        if (lane < 5) a += x[s * 5 + lane] * wt;
    }
    if (lane < 5) a = (a + x[d * 5 + lane] * disd) * disd;
    float xa0 = __shfl_sync(0xffffffffu, a, 0);
    float xa1 = __shfl_sync(0xffffffffu, a, 1);
    float xa2 = __shfl_sync(0xffffffffu, a, 2);
    float xa3 = __shfl_sync(0xffffffffu, a, 3);
    float xa4 = __shfl_sync(0xffffffffu, a, 4);

    int c0 = lane, c1 = lane + 32;
    float h0 = xa0 * sW[c0] + xa1 * sW[64 + c0] + xa2 * sW[128 + c0]
             + xa3 * sW[192 + c0] + xa4 * sW[256 + c0];
    float h1 = xa0 * sW[c1] + xa1 * sW[64 + c1] + xa2 * sW[128 + c1]
             + xa3 * sW[192 + c1] + xa4 * sW[256 + c1];
    C[(size_t)d * 64 + c0] = h0;
    C[(size_t)d * 64 + c1] = h1;
    atomicAdd(&ssum[c0], h0); atomicAdd(&ssq[c0], h0 * h0);
    atomicAdd(&ssum[c1], h1); atomicAdd(&ssq[c1], h1 * h1);
    __syncthreads();
    if (tid < 64) {
        atomicAdd(&g_bnsum[tid], ssum[tid]);
        atomicAdd(&g_bnsq[tid], ssq[tid]);
    }
}

// ---------------- SAGE aggregation with fused BN1+ReLU ----------------------
__global__ __launch_bounds__(256) void k_sage_agg_bn(
    const float* __restrict__ C1,
    const float* __restrict__ gam, const float* __restrict__ bet,
    float* __restrict__ P)
{
    int w = threadIdx.x >> 5;
    int d = blockIdx.x * 8 + w;
    int lane = threadIdx.x & 31;
    int st = g_rowptr[d], deg = g_rowptr[d + 1] - st;
    int half = lane >> 4;
    int q = lane & 15;             // float4 chunk of 64 ch
    float sc[4], sh[4];
    float inv_n = 1.0f / (float)NN;
#pragma unroll
    for (int j = 0; j < 4; j++) {
        int c = q * 4 + j;
        float mean = g_bnsum[c] * inv_n;
        float var = g_bnsq[c] * inv_n - mean * mean;
        float s = rsqrtf(var + BN_EPS) * gam[c];
        sc[j] = s;
        sh[j] = bet[c] - mean * s;
    }
    const float4* C4 = (const float4*)C1;   // row stride 16
    float4 a = make_float4(0.f, 0.f, 0.f, 0.f);
    for (int i = 0; i < deg; i += 2) {
        int idx = i + half;
        if (idx < deg) {
            int s = g_csr[st + idx];
            float4 v = C4[(size_t)s * 16 + q];
            a.x += fmaxf(fmaf(v.x, sc[0], sh[0]), 0.f);
            a.y += fmaxf(fmaf(v.y, sc[1], sh[1]), 0.f);
            a.z += fmaxf(fmaf(v.z, sc[2], sh[2]), 0.f);
            a.w += fmaxf(fmaf(v.w, sc[3], sh[3]), 0.f);
        }
    }
    a.x += __shfl_xor_sync(0xffffffffu, a.x, 16);
    a.y += __shfl_xor_sync(0xffffffffu, a.y, 16);
    a.z += __shfl_xor_sync(0xffffffffu, a.z, 16);
    a.w += __shfl_xor_sync(0xffffffffu, a.w, 16);
    float4 vd = C4[(size_t)d * 16 + q];
    float4 hd;
    hd.x = fmaxf(fmaf(vd.x, sc[0], sh[0]), 0.f);
    hd.y = fmaxf(fmaf(vd.y, sc[1], sh[1]), 0.f);
    hd.z = fmaxf(fmaf(vd.z, sc[2], sh[2]), 0.f);
    hd.w = fmaxf(fmaf(vd.w, sc[3], sh[3]), 0.f);
    if (lane < 16) {
        float inv = 1.f / (float)max(deg, 1);
        float4* P4 = (float4*)P;
        P4[(size_t)d * 32 + q] = make_float4(a.x * inv, a.y * inv, a.z * inv, a.w * inv);
        P4[(size_t)d * 32 + 16 + q] = hd;
    }
}

// ---------------- FP16 tensor-core GEMM (BK=16) + fused BN-stat epilogue ----
__device__ __forceinline__ void st_half4(__half* p, float4 v) {
    ((__half2*)p)[0] = __floats2half2_rn(v.x, v.y);
    ((__half2*)p)[1] = __floats2half2_rn(v.z, v.w);
}

__global__ __launch_bounds__(256, 2) void k_gemm_f16(
    const float* __restrict__ A,
    const float* __restrict__ W1, const float* __restrict__ W2, int ksplit,
    float* __restrict__ C, int M, int K, int Nn, int gatmode, int statoff)
{
    __shared__ __half As[128][24];
    __shared__ __half Bs[16][136];
    __shared__ float red[2][128][2];

    int tid = threadIdx.x;
    int warp = tid >> 5;
    int wm = warp >> 2;
    int wn = warp & 3;
    int row0 = blockIdx.y * 128, col0 = blockIdx.x * 128;

    int a_r[2], a_c[2];
#pragma unroll
    for (int i = 0; i < 2; i++) {
        int s = tid * 2 + i;
        a_r[i] = s >> 2;
        a_c[i] = (s & 3) * 4;
    }
    int b_r[2], b_c[2];
#pragma unroll
    for (int i = 0; i < 2; i++) {
        int s = tid + 256 * i;
        b_r[i] = s >> 5;
        b_c[i] = (s & 31) * 4;
    }

    const float* Abase = A + (size_t)row0 * K;

    float4 cA[2], cB[2];
#pragma unroll
    for (int i = 0; i < 2; i++) {
        cA[i] = *(const float4*)(Abase + (size_t)a_r[i] * K + a_c[i]);
        int k = b_r[i];
        const float* wp;
        if (gatmode) wp = W1 + (size_t)(k & 127) * 1024 + (k >> 7) * 256;
        else wp = (k < ksplit) ? (W1 + (size_t)k * Nn)
                               : (W2 + (size_t)(k - ksplit) * Nn);
        cB[i] = *(const float4*)(wp + col0 + b_c[i]);
    }

    wmma::fragment<wmma::accumulator, 16, 16, 16, float> acc[4][2];
#pragma unroll
    for (int i = 0; i < 4; i++)
#pragma unroll
        for (int j = 0; j < 2; j++) wmma::fill_fragment(acc[i][j], 0.f);

    for (int k0 = 0; k0 < K; k0 += 16) {
#pragma unroll
        for (int i = 0; i < 2; i++) {
            st_half4(&As[a_r[i]][a_c[i]], cA[i]);
            st_half4(&Bs[b_r[i]][b_c[i]], cB[i]);
        }
        __syncthreads();
        if (k0 + 16 < K) {
#pragma unroll
            for (int i = 0; i < 2; i++) {
                cA[i] = *(const float4*)(Abase + (size_t)a_r[i] * K + (k0 + 16) + a_c[i]);
                int k = k0 + 16 + b_r[i];
                const float* wp;
                if (gatmode) wp = W1 + (size_t)(k & 127) * 1024 + (k >> 7) * 256;
                else wp = (k < ksplit) ? (W1 + (size_t)k * Nn)
                                       : (W2 + (size_t)(k - ksplit) * Nn);
                cB[i] = *(const float4*)(wp + col0 + b_c[i]);
            }
        }
        {
            wmma::fragment<wmma::matrix_a, 16, 16, 16, __half, wmma::row_major> af[4];
            wmma::fragment<wmma::matrix_b, 16, 16, 16, __half, wmma::row_major> bf[2];
#pragma unroll
            for (int i = 0; i < 4; i++)
                wmma::load_matrix_sync(af[i], &As[wm * 64 + i * 16][0], 24);
#pragma unroll
            for (int j = 0; j < 2; j++)
                wmma::load_matrix_sync(bf[j], &Bs[0][wn * 32 + j * 16], 136);
#pragma unroll
            for (int i = 0; i < 4; i++)
#pragma unroll
                for (int j = 0; j < 2; j++)
                    wmma::mma_sync(acc[i][j], af[i], bf[j], acc[i][j]);
        }
        __syncthreads();
    }

#pragma unroll
    for (int i = 0; i < 4; i++)
#pragma unroll
        for (int j = 0; j < 2; j++) {
            int gr = row0 + wm * 64 + i * 16;
            int gc = col0 + wn * 32 + j * 16;
            wmma::store_matrix_sync(C + (size_t)gr * Nn + gc, acc[i][j], Nn,
                                    wmma::mem_row_major);
        }

    if (statoff >= 0) {
        __syncthreads();
        int c = tid & 127, rh = tid >> 7;
        const float* cp = C + (size_t)(row0 + rh * 64) * Nn + col0 + c;
        float s = 0.f, q = 0.f;
#pragma unroll 4
        for (int r = 0; r < 64; r++) {
            float v = cp[(size_t)r * Nn];
            s += v;
            q += v * v;
        }
        red[rh][c][0] = s;
        red[rh][c][1] = q;
        __syncthreads();
        if (rh == 0) {
            s += red[1][c][0];
            q += red[1][c][1];
            atomicAdd(&g_bnsum[statoff + col0 + c], s);
            atomicAdd(&g_bnsq[statoff + col0 + c], q);
        }
    }
}

// ---------------- layer-4 GCN gather with fused BN3+ReLU (MLP 4) -----------
__global__ __launch_bounds__(256) void k_gcn_agg4_bn(
    const float* __restrict__ C3,
    const float* __restrict__ gam, const float* __restrict__ bet,
    float* __restrict__ out)
{
    int tid = threadIdx.x;
    int d = blockIdx.x * 4 + (tid >> 6);
    int t = tid & 63;
    int st = g_rowptr[d], deg = g_rowptr[d + 1] - st;
    float disd = g_dis[d];
    float sc[4], sh[4];
    float inv_n = 1.0f / (float)NN;
#pragma unroll
    for (int j = 0; j < 4; j++) {
        int c = t * 4 + j;
        float mean = g_bnsum[1024 + c] * inv_n;
        float var = g_bnsq[1024 + c] * inv_n - mean * mean;
        float s = rsqrtf(var + BN_EPS) * gam[c];
        sc[j] = s;
        sh[j] = bet[c] - mean * s;
    }
    const float4* in4 = (const float4*)C3;
    float4 a = make_float4(0.f, 0.f, 0.f, 0.f);
    int i = 0;
    for (; i + 4 <= deg; i += 4) {
        int s0 = g_csr[st + i], s1 = g_csr[st + i + 1];
        int s2 = g_csr[st + i + 2], s3 = g_csr[st + i + 3];
        float w0 = g_dis[s0], w1 = g_dis[s1], w2 = g_dis[s2], w3 = g_dis[s3];
        float4 v0 = in4[(size_t)s0 * 64 + t];
        float4 v1 = in4[(size_t)s1 * 64 + t];
        float4 v2 = in4[(size_t)s2 * 64 + t];
        float4 v3 = in4[(size_t)s3 * 64 + t];
        a.x += fmaxf(fmaf(v0.x, sc[0], sh[0]), 0.f) * w0 + fmaxf(fmaf(v1.x, sc[0], sh[0]), 0.f) * w1
             + fmaxf(fmaf(v2.x, sc[0], sh[0]), 0.f) * w2 + fmaxf(fmaf(v3.x, sc[0], sh[0]), 0.f) * w3;
        a.y += fmaxf(fmaf(v0.y, sc[1], sh[1]), 0.f) * w0 + fmaxf(fmaf(v1.y, sc[1], sh[1]), 0.f) * w1
             + fmaxf(fmaf(v2.y, sc[1], sh[1]), 0.f) * w2 + fmaxf(fmaf(v3.y, sc[1], sh[1]), 0.f) * w3;
        a.z += fmaxf(fmaf(v0.z, sc[2], sh[2]), 0.f) * w0 + fmaxf(fmaf(v1.z, sc[2], sh[2]), 0.f) * w1
             + fmaxf(fmaf(v2.z, sc[2], sh[2]), 0.f) * w2 + fmaxf(fmaf(v3.z, sc[2], sh[2]), 0.f) * w3;
        a.w += fmaxf(fmaf(v0.w, sc[3], sh[3]), 0.f) * w0 + fmaxf(fmaf(v1.w, sc[3], sh[3]), 0.f) * w1
             + fmaxf(fmaf(v2.w, sc[3], sh[3]), 0.f) * w2 + fmaxf(fmaf(v3.w, sc[3], sh[3]), 0.f) * w3;
    }
    for (; i < deg; i++) {
        int s0 = g_csr[st + i];
        float w0 = g_dis[s0];
        float4 v0 = in4[(size_t)s0 * 64 + t];
        a.x += fmaxf(fmaf(v0.x, sc[0], sh[0]), 0.f) * w0;
        a.y += fmaxf(fmaf(v0.y, sc[1], sh[1]), 0.f) * w0;
        a.z += fmaxf(fmaf(v0.z, sc[2], sh[2]), 0.f) * w0;
        a.w += fmaxf(fmaf(v0.w, sc[3], sh[3]), 0.f) * w0;
    }
    float4 v = in4[(size_t)d * 64 + t];
    a.x += fmaxf(fmaf(v.x, sc[0], sh[0]), 0.f) * disd;
    a.y += fmaxf(fmaf(v.y, sc[1], sh[1]), 0.f) * disd;
    a.z += fmaxf(fmaf(v.z, sc[2], sh[2]), 0.f) * disd;
    a.w += fmaxf(fmaf(v.w, sc[3], sh[3]), 0.f) * disd;
    a.x *= disd; a.y *= disd; a.z *= disd; a.w *= disd;
    ((float4*)out)[(size_t)d * 64 + t] = a;
}

// ---------------- BN2 apply + es/ed fused ------------------------------------
__global__ __launch_bounds__(256) void k_bn2_esed(
    const float* __restrict__ C2, const float* __restrict__ gam,
    const float* __restrict__ bet, float* __restrict__ D)
{
    __shared__ float swa[1024];
    int tid = threadIdx.x;
    for (int t = tid; t < 1024; t += 256) swa[t] = g_wa[t];
    __syncthreads();
    int w = tid >> 5, lane = tid & 31;
    int n = blockIdx.x * 8 + w;
    float4 v = ((const float4*)C2)[(size_t)n * 32 + lane];
    float inv_n = 1.0f / (float)NN;
    float r[4] = {v.x, v.y, v.z, v.w};
#pragma unroll
    for (int j = 0; j < 4; j++) {
        int c = lane * 4 + j;
        float mean = g_bnsum[512 + c] * inv_n;
        float var = g_bnsq[512 + c] * inv_n - mean * mean;
        float y = (r[j] - mean) * rsqrtf(var + BN_EPS) * gam[c] + bet[c];
        r[j] = fmaxf(y, 0.f);
    }
    ((float4*)D)[(size_t)n * 32 + lane] = make_float4(r[0], r[1], r[2], r[3]);

    float p[8];
#pragma unroll
    for (int s = 0; s < 2; s++)
#pragma unroll
        for (int h = 0; h < 4; h++) {
            float4 wv = ((const float4*)swa)[(s * 512 + h * 128) / 4 + lane];
            p[s * 4 + h] = r[0] * wv.x + r[1] * wv.y + r[2] * wv.z + r[3] * wv.w;
        }
#pragma unroll
    for (int o = 16; o > 0; o >>= 1)
#pragma unroll
        for (int j = 0; j < 8; j++)
            p[j] += __shfl_xor_sync(0xffffffffu, p[j], o);
    if (lane < 4) g_es[n * 4 + lane] = p[lane];
    else if (lane < 8) g_ed[n * 4 + (lane - 4)] = p[lane];
}

__device__ __forceinline__ float leaky02(float x) { return x > 0.f ? x : 0.2f * x; }

// ---------------- GAT aggregation: ONE warp per node, 4 heads --------------
// Per edge: D row loaded once, scaled by 4 cached alphas (float4 per edge).
// 8 warps/block = 8 nodes. smem: se4 (exp per head) + ss (src).
__global__ __launch_bounds__(256) void k_gat_agg(const float* __restrict__ D,
                                                 float* __restrict__ agg)
{
    __shared__ float4 se4[8][66];
    __shared__ int    ss[8][66];
    int warp = threadIdx.x >> 5;
    int lane = threadIdx.x & 31;
    int d = blockIdx.x * 8 + warp;
    int st = g_rowptr[d], deg = g_rowptr[d + 1] - st;
    int tot = deg + 1;   // self loop at index deg
    float4 edv = ((const float4*)g_ed)[d];
    float4 esd = ((const float4*)g_es)[d];
    float4 eself;
    eself.x = leaky02(esd.x + edv.x);
    eself.y = leaky02(esd.y + edv.y);
    eself.z = leaky02(esd.z + edv.z);
    eself.w = leaky02(esd.w + edv.w);

    const float4* D4 = (const float4*)D;
    float4 a0 = make_float4(0.f, 0.f, 0.f, 0.f);
    float4 a1 = a0, a2 = a0, a3 = a0;

    if (tot <= 64) {
        // phase 1: e per edge per head (float4), cached
        for (int i = lane; i < tot; i += 32) {
            int s = (i < deg) ? g_csr[st + i] : d;
            ss[warp][i] = s;
            if (i < deg) {
                float4 es = ((const float4*)g_es)[s];
                float4 e;
                e.x = leaky02(es.x + edv.x);
                e.y = leaky02(es.y + edv.y);
                e.z = leaky02(es.z + edv.z);
                e.w = leaky02(es.w + edv.w);
                se4[warp][i] = e;
            } else {
                se4[warp][i] = eself;
            }
        }
        __syncwarp();
        // phase 2: per-head max
        float4 m = make_float4(-3.4e38f, -3.4e38f, -3.4e38f, -3.4e38f);
        for (int i = lane; i < tot; i += 32) {
            float4 e = se4[warp][i];
            m.x = fmaxf(m.x, e.x); m.y = fmaxf(m.y, e.y);
            m.z = fmaxf(m.z, e.z); m.w = fmaxf(m.w, e.w);
        }
#pragma unroll
        for (int o = 16; o > 0; o >>= 1) {
            m.x = fmaxf(m.x, __shfl_xor_sync(0xffffffffu, m.x, o));
            m.y = fmaxf(m.y, __shfl_xor_sync(0xffffffffu, m.y, o));
            m.z = fmaxf(m.z, __shfl_xor_sync(0xffffffffu, m.z, o));
            m.w = fmaxf(m.w, __shfl_xor_sync(0xffffffffu, m.w, o));
        }
        // phase 3: exp + per-head sum, overwrite cache
        float4 z = make_float4(0.f, 0.f, 0.f, 0.f);
        for (int i = lane; i < tot; i += 32) {
            float4 e = se4[warp][i];
            e.x = __expf(e.x - m.x); e.y = __expf(e.y - m.y);
            e.z = __expf(e.z - m.z); e.w = __expf(e.w - m.w);
            se4[warp][i] = e;
            z.x += e.x; z.y += e.y; z.z += e.z; z.w += e.w;
        }
        __syncwarp();
#pragma unroll
        for (int o = 16; o > 0; o >>= 1) {
            z.x += __shfl_xor_sync(0xffffffffu, z.x, o);
            z.y += __shfl_xor_sync(0xffffffffu, z.y, o);
            z.z += __shfl_xor_sync(0xffffffffu, z.z, o);
            z.w += __shfl_xor_sync(0xffffffffu, z.w, o);
        }
        float4 invz = make_float4(1.f / z.x, 1.f / z.y, 1.f / z.z, 1.f / z.w);
        // phase 4: load each row ONCE, accumulate 4 heads
        int i = 0;
        for (; i + 2 <= tot; i += 2) {
            int sA = ss[warp][i], sB = ss[warp][i + 1];
            float4 alA = se4[warp][i], alB = se4[warp][i + 1];
            float4 vA = D4[(size_t)sA * 32 + lane];
            float4 vB = D4[(size_t)sB * 32 + lane];
            float wA0 = alA.x * invz.x, wB0 = alB.x * invz.x;
            float wA1 = alA.y * invz.y, wB1 = alB.y * invz.y;
            float wA2 = alA.z * invz.z, wB2 = alB.z * invz.z;
            float wA3 = alA.w * invz.w, wB3 = alB.w * invz.w;
            a0.x += vA.x * wA0 + vB.x * wB0; a0.y += vA.y * wA0 + vB.y * wB0;
            a0.z += vA.z * wA0 + vB.z * wB0; a0.w += vA.w * wA0 + vB.w * wB0;
            a1.x += vA.x * wA1 + vB.x * wB1; a1.y += vA.y * wA1 + vB.y * wB1;
            a1.z += vA.z * wA1 + vB.z * wB1; a1.w += vA.w * wA1 + vB.w * wB1;
            a2.x += vA.x * wA2 + vB.x * wB2; a2.y += vA.y * wA2 + vB.y * wB2;
            a2.z += vA.z * wA2 + vB.z * wB2; a2.w += vA.w * wA2 + vB.w * wB2;
            a3.x += vA.x * wA3 + vB.x * wB3; a3.y += vA.y * wA3 + vB.y * wB3;
            a3.z += vA.z * wA3 + vB.z * wB3; a3.w += vA.w * wA3 + vB.w * wB3;
        }
        if (i < tot) {
            int sA = ss[warp][i];
            float4 alA = se4[warp][i];
            float4 vA = D4[(size_t)sA * 32 + lane];
            float wA0 = alA.x * invz.x, wA1 = alA.y * invz.y;
            float wA2 = alA.z * invz.z, wA3 = alA.w * invz.w;
            a0.x += vA.x * wA0; a0.y += vA.y * wA0; a0.z += vA.z * wA0; a0.w += vA.w * wA0;
            a1.x += vA.x * wA1; a1.y += vA.y * wA1; a1.z += vA.z * wA1; a1.w += vA.w * wA1;
            a2.x += vA.x * wA2; a2.y += vA.y * wA2; a2.z += vA.z * wA2; a2.w += vA.w * wA2;
            a3.x += vA.x * wA3; a3.y += vA.y * wA3; a3.z += vA.z * wA3; a3.w += vA.w * wA3;
        }
    } else {
        // fallback (deg > 63): recompute per edge, still single row load
        float4 m = eself;
        for (int i = lane; i < deg; i += 32) {
            float4 es = ((const float4*)g_es)[g_csr[st + i]];
            m.x = fmaxf(m.x, leaky02(es.x + edv.x));
            m.y = fmaxf(m.y, leaky02(es.y + edv.y));
            m.z = fmaxf(m.z, leaky02(es.z + edv.z));
            m.w = fmaxf(m.w, leaky02(es.w + edv.w));
        }
#pragma unroll
        for (int o = 16; o > 0; o >>= 1) {
            m.x = fmaxf(m.x, __shfl_xor_sync(0xffffffffu, m.x, o));
            m.y = fmaxf(m.y, __shfl_xor_sync(0xffffffffu, m.y, o));
            m.z = fmaxf(m.z, __shfl_xor_sync(0xffffffffu, m.z, o));
            m.w = fmaxf(m.w, __shfl_xor_sync(0xffffffffu, m.w, o));
        }
        float4 z = make_float4(0.f, 0.f, 0.f, 0.f);
        if (lane == 0) {
            z.x = __expf(eself.x - m.x); z.y = __expf(eself.y - m.y);
            z.z = __expf(eself.z - m.z); z.w = __expf(eself.w - m.w);
        }
        for (int i = lane; i < deg; i += 32) {
            float4 es = ((const float4*)g_es)[g_csr[st + i]];
            z.x += __expf(leaky02(es.x + edv.x) - m.x);
            z.y += __expf(leaky02(es.y + edv.y) - m.y);
            z.z += __expf(leaky02(es.z + edv.z) - m.z);
            z.w += __expf(leaky02(es.w + edv.w) - m.w);
        }
#pragma unroll
        for (int o = 16; o > 0; o >>= 1) {
            z.x += __shfl_xor_sync(0xffffffffu, z.x, o);
            z.y += __shfl_xor_sync(0xffffffffu, z.y, o);
            z.z += __shfl_xor_sync(0xffffffffu, z.z, o);
            z.w += __shfl_xor_sync(0xffffffffu, z.w, o);
        }
        float4 invz = make_float4(1.f / z.x, 1.f / z.y, 1.f / z.z, 1.f / z.w);
        for (int i = 0; i <= deg; i++) {
            int s = (i < deg) ? g_csr[st + i] : d;
            float4 es = ((const float4*)g_es)[s];
            float w0 = __expf(leaky02(es.x + edv.x) - m.x) * invz.x;
            float w1 = __expf(leaky02(es.y + edv.y) - m.y) * invz.y;
            float w2 = __expf(leaky02(es.z + edv.z) - m.z) * invz.z;
            float w3 = __expf(leaky02(es.w + edv.w) - m.w) * invz.w;
            float4 v = D4[(size_t)s * 32 + lane];
            a0.x += v.x * w0; a0.y += v.y * w0; a0.z += v.z * w0; a0.w += v.w * w0;
            a1.x += v.x * w1; a1.y += v.y * w1; a1.z += v.z * w1; a1.w += v.w * w1;
            a2.x += v.x * w2; a2.y += v.y * w2; a2.z += v.z * w2; a2.w += v.w * w2;
            a3.x += v.x * w3; a3.y += v.y * w3; a3.z += v.z * w3; a3.w += v.w * w3;
        }
    }
    float4* O = (float4*)agg + (size_t)d * 128;
    O[lane]       = a0;
    O[32 + lane]  = a1;
    O[64 + lane]  = a2;
    O[96 + lane]  = a3;
}

// ---------------- pooling (fused BN4+ReLU), atomic, grid (GG, 8) ------------
__global__ void k_pool_bn(const float* __restrict__ C4buf,
                          const float* __restrict__ gam, const float* __restrict__ bet)
{
    int g = blockIdx.x;
    int chunk = blockIdx.y;      // 0..7
    int c4 = threadIdx.x;        // 128 (float4 over 512 ch)
    int st = g_gstart[g], en = g_gstart[g + 1];
    int cnt = en - st;
    int lo = st + (cnt * chunk) / 8;
    int hi = st + (cnt * (chunk + 1)) / 8;
    float sc[4], sh[4];
    float inv_n = 1.0f / (float)NN;
#pragma unroll
    for (int j = 0; j < 4; j++) {
        int c = c4 * 4 + j;
        float mean = g_bnsum[1536 + c] * inv_n;
        float var = g_bnsq[1536 + c] * inv_n - mean * mean;
        float s = rsqrtf(var + BN_EPS) * gam[c];
        sc[j] = s;
        sh[j] = bet[c] - mean * s;
    }
    const float4* D4 = (const float4*)C4buf;
    float4 s = make_float4(0.f, 0.f, 0.f, 0.f);
    float4 m = make_float4(0.f, 0.f, 0.f, 0.f);   // post-ReLU values >= 0
    for (int i = lo; i < hi; i++) {
        float4 v = D4[(size_t)i * 128 + c4];
        v.x = fmaxf(fmaf(v.x, sc[0], sh[0]), 0.f);
        v.y = fmaxf(fmaf(v.y, sc[1], sh[1]), 0.f);
        v.z = fmaxf(fmaf(v.z, sc[2], sh[2]), 0.f);
        v.w = fmaxf(fmaf(v.w, sc[3], sh[3]), 0.f);
        s.x += v.x; s.y += v.y; s.z += v.z; s.w += v.w;
        m.x = fmaxf(m.x, v.x); m.y = fmaxf(m.y, v.y);
        m.z = fmaxf(m.z, v.z); m.w = fmaxf(m.w, v.w);
    }
    if (lo < hi) {
        float* sp = &g_pooled[g * 1024 + c4 * 4];
        atomicAdd(sp + 0, s.x); atomicAdd(sp + 1, s.y);
        atomicAdd(sp + 2, s.z); atomicAdd(sp + 3, s.w);
        int* mp = (int*)&g_pooled[g * 1024 + 512 + c4 * 4];
        atomicMax(mp + 0, __float_as_int(m.x));
        atomicMax(mp + 1, __float_as_int(m.y));
        atomicMax(mp + 2, __float_as_int(m.z));
        atomicMax(mp + 3, __float_as_int(m.w));
    }
}

// ---------------- FC (divides mean-sum by cnt on load) ----------------------
__global__ __launch_bounds__(128) void k_fc(const float* __restrict__ W,
                                            const float* __restrict__ bias,
                                            float* __restrict__ out)
{
    __shared__ float sp[4][1024];
    int tid = threadIdx.x;
    int j = blockIdx.x * 128 + tid;
    int g0 = blockIdx.y * 4;
    for (int t = tid; t < 4 * 1024; t += 128) {
        int gg = g0 + (t >> 10);
        int c = t & 1023;
        float v = g_pooled[gg * 1024 + c];
        if (c < 512) {
            int cnt = g_gstart[gg + 1] - g_gstart[gg];
            v *= 1.f / (float)max(cnt, 1);
        }
        sp[t >> 10][c] = v;
    }
    __syncthreads();
    float acc[4] = {0.f, 0.f, 0.f, 0.f};
#pragma unroll 4
    for (int kk = 0; kk < 1024; kk++) {
        float wv = W[(size_t)kk * 1024 + j];
#pragma unroll
        for (int g = 0; g < 4; g++) acc[g] += sp[g][kk] * wv;
    }
    float bv = bias[j];
#pragma unroll
    for (int g = 0; g < 4; g++) out[(size_t)(g0 + g) * 1024 + j] = acc[g] + bv;
}

// ---------------- host orchestration ---------------------------------------
extern "C" void kernel_launch(void* const* d_in, const int* in_sizes, int n_in,
                              void* d_out, int out_size)
{
    const float* x        = (const float*)d_in[0];
    const int*   ei       = (const int*)  d_in[1];
    const int*   batch    = (const int*)  d_in[2];
    const float* gcn1_w   = (const float*)d_in[3];
    const float* sage_wl  = (const float*)d_in[5];
    const float* sage_wr  = (const float*)d_in[6];
    const float* gat_w    = (const float*)d_in[8];
    const float* gat_asrc = (const float*)d_in[9];
    const float* gat_adst = (const float*)d_in[10];
    const float* gcn4_w   = (const float*)d_in[12];
    const float* bn1_g = (const float*)d_in[14]; const float* bn1_b = (const float*)d_in[15];
    const float* bn2_g = (const float*)d_in[16]; const float* bn2_b = (const float*)d_in[17];
    const float* bn3_g = (const float*)d_in[18]; const float* bn3_b = (const float*)d_in[19];
    const float* bn4_g = (const float*)d_in[20]; const float* bn4_b = (const float*)d_in[21];
    const float* fc_w  = (const float*)d_in[22]; const float* fc_b  = (const float*)d_in[23];
    float* out = (float*)d_out;

    const int* src = ei;
    const int* dst = ei + EE;

    float *A, *B, *C, *D;
    cudaGetSymbolAddress((void**)&A, g_bufA);
    cudaGetSymbolAddress((void**)&B, g_bufB);
    cudaGetSymbolAddress((void**)&C, g_bufC);
    cudaGetSymbolAddress((void**)&D, g_bufD);

    // setup (zero + wa + gstart) and graph build
    k_setup<<<69, 256>>>(gat_w, gat_asrc, gat_adst, batch);
    k_deg<<<EE / 256, 256>>>(dst);
    k_scan<<<1, 1024>>>();
    k_csr_fill<<<EE / 256, 256>>>(src, dst);

    // ---- layer 1: fused gather + GEMV + BN stats ----
    k_l1<<<NN / 8, 256>>>(x, gcn1_w, C);

    // ---- layer 2: SAGE(64->128) with fused BN1; single GEMM + stats ----
    k_sage_agg_bn<<<NN / 8, 256>>>(C, bn1_g, bn1_b, B);
    k_gemm_f16<<<dim3(1, NN / 128), 256>>>(B, sage_wl, sage_wr, 64, C, NN, 128, 128, 0, 512);
    k_bn2_esed<<<NN / 8, 256>>>(C, bn2_g, bn2_b, D);

    // ---- layer 3: GAT aggregate-then-transform + stats ----
    k_gat_agg<<<NN / 8, 256>>>(D, A);
    k_gemm_f16<<<dim3(2, NN / 128), 256>>>(A, gat_w, nullptr, 0, C, NN, 512, 256, 1, 1024);

    // ---- layer 4: GCN with fused BN3 gather, GEMM + stats ----
    k_gcn_agg4_bn<<<NN / 4, 256>>>(C, bn3_g, bn3_b, B);
    k_gemm_f16<<<dim3(4, NN / 128), 256>>>(B, gcn4_w, gcn4_w, 256, C, NN, 256, 512, 0, 1536);

    // ---- pooling (BN4 fused, parallel atomic) + FC ----
    k_pool_bn<<<dim3(GG, 8), 128>>>(C, bn4_g, bn4_b);
    k_fc<<<dim3(8, 8), 128>>>(fc_w, fc_b, out);
}